// round 7
// baseline (speedup 1.0000x reference)
#include <cuda_runtime.h>
#include <math.h>

#define BB 2
#define NN 2048
#define EE 64
#define KK 2
#define FIN 18
#define MAXDEG_ADJ 64
#define MAXDEG_A2 512
#define MAXDEG_IN 64
#define GG 128
#define TT 256
#define FULLMASK 0xffffffffu

// ---------------- device scratch ----------------
__device__ float g_h[BB*NN*EE];
__device__ float g_zp[BB*NN*2*EE];
__device__ float g_ssrc[2*BB*NN];
__device__ float g_sdst[2*BB*NN];
__device__ float g_hbar[BB*EE];
__device__ float g_zmean[2*BB*EE];
__device__ float g_aggs[BB*NN*KK*EE];
__device__ unsigned short g_nbr_adj[BB*NN*MAXDEG_ADJ];
__device__ unsigned short g_nbr_a2[BB*NN*MAXDEG_A2];
__device__ unsigned short g_rin[BB*NN*MAXDEG_IN];
__device__ int g_deg_adj[BB*NN];
__device__ int g_deg_a2[BB*NN];
__device__ int g_rdeg[BB*NN];
__device__ unsigned g_adjbit[BB*NN*(NN/32)];
__device__ float g_nw[BB*NN];
__device__ float g_dv[BB*NN];
__device__ float g_enw[BB*NN];
__device__ float g_Z[BB*NN];
__device__ float g_s10[BB*NN];
__device__ unsigned g_gmaxu[BB];
__device__ int g_bar_cnt;
__device__ volatile int g_bar_gen;

__device__ __forceinline__ float warpSum(float v){
    #pragma unroll
    for (int o=16;o;o>>=1) v += __shfl_xor_sync(FULLMASK, v, o);
    return v;
}
__device__ __forceinline__ float sigmoidf_(float x){ return 1.0f/(1.0f+__expf(-x)); }

__device__ __forceinline__ void gridBarrier(){
    __syncthreads();
    if (threadIdx.x == 0){
        __threadfence();
        int gen = g_bar_gen;
        if (atomicAdd(&g_bar_cnt, 1) == GG-1){
            g_bar_cnt = 0;
            __threadfence();
            g_bar_gen = gen + 1;
        } else {
            while (g_bar_gen == gen) { }
        }
        __threadfence();
    }
    __syncthreads();
}

// smem layout (floats): max phase = gru: 12288+12288+512*3+64 = 26176 floats
#define SMEM_FLOATS 26176

__global__ __launch_bounds__(TT,1) void K_all(
    const float* __restrict__ feat, const float* __restrict__ emb,
    const float* __restrict__ demands, const float* __restrict__ neigh,
    const float* __restrict__ enc_W0, const float* __restrict__ enc_b0,
    const float* __restrict__ enc_W1, const float* __restrict__ enc_b1,
    const float* __restrict__ attn_W, const float* __restrict__ a_src,
    const float* __restrict__ a_dst, const float* __restrict__ nbr_q,
    const float* __restrict__ gru_W, const float* __restrict__ gru_U,
    const float* __restrict__ gru_b,
    const float* __restrict__ dec_W0, const float* __restrict__ dec_b0,
    const float* __restrict__ dec_W1, const float* __restrict__ dec_b1,
    const float* __restrict__ dual_W0, const float* __restrict__ dual_b0,
    const float* __restrict__ dual_W1, const float* __restrict__ dual_b1,
    float* __restrict__ out)
{
    extern __shared__ __align__(16) float smf[];
    int bid = blockIdx.x, tid = threadIdx.x;
    int w = tid>>5, lane = tid&31;

    // ================= init =================
    for (int i = bid*TT+tid; i < BB*NN; i += GG*TT) g_rdeg[i] = 0;
    if (bid==0){
        if (tid < BB){ out[tid] = 0.f; g_gmaxu[tid] = 0u; }
        if (tid < BB*EE) g_hbar[tid] = 0.f;
    }
    gridBarrier();

    // ================= encoder =================
    {
        float* sW0 = smf;          // 18*64
        float* sW1 = smf+1152;     // 64*64
        float* sx  = smf+5248;     // 4*18
        float* st  = smf+5328;     // 4*64
        for (int i=tid;i<FIN*EE;i+=TT) sW0[i]=enc_W0[i];
        for (int i=tid;i<EE*EE;i+=TT)  sW1[i]=enc_W1[i];
        int g = tid>>6, e = tid&63;
        float hb0=0.f, hb1=0.f;
        for (int vb=bid; vb<BB*NN/4; vb+=GG){
            int gn = vb*4+g;
            __syncthreads();
            if (e < 16)       sx[g*FIN+e] = emb[gn*16+e];
            else if (e < FIN) sx[g*FIN+e] = feat[gn*2+(e-16)];
            __syncthreads();
            float acc = enc_b0[e];
            #pragma unroll
            for (int d=0; d<FIN; d++) acc += sx[g*FIN+d]*sW0[d*EE+e];
            st[g*EE+e] = tanhf(acc);
            __syncthreads();
            float acc2 = enc_b1[e];
            #pragma unroll
            for (int d=0; d<EE; d++) acc2 += st[g*EE+d]*sW1[d*EE+e];
            float hv = tanhf(acc2);
            g_h[gn*EE+e] = hv;
            __syncthreads();
            st[g*EE+e] = hv;
            __syncthreads();
            if (tid < EE){
                float s4 = st[tid]+st[EE+tid]+st[2*EE+tid]+st[3*EE+tid];
                if (vb >= NN/4) hb1 += s4; else hb0 += s4;
            }
        }
        if (tid < EE){
            atomicAdd(&g_hbar[tid],    hb0);
            atomicAdd(&g_hbar[EE+tid], hb1);
        }
    }

    // ================= CSR build =================
    {
        for (int vb=bid; vb<KK*BB*NN/8; vb+=GG){
            int row = vb*8 + w;
            int k  = row / (BB*NN);
            int bn = row % (BB*NN);
            int b_ = bn / NN, i_ = bn % NN;
            const float* src = neigh + (size_t)row * NN;
            unsigned short* dst = (k==0) ? (g_nbr_adj + (size_t)bn*MAXDEG_ADJ)
                                         : (g_nbr_a2  + (size_t)bn*MAXDEG_A2);
            int cap = (k==0) ? MAXDEG_ADJ : MAXDEG_A2;
            int deg = 0;
            #pragma unroll 4
            for (int c=0; c<NN/32; c++){
                int j = c*32 + lane;
                bool p = src[j] > 0.0f;
                unsigned bal = __ballot_sync(FULLMASK, p);
                if (k==0 && lane==0) g_adjbit[(size_t)bn*(NN/32) + c] = bal;
                int pre = __popc(bal & ((1u<<lane)-1u));
                if (p){
                    int pos = deg + pre;
                    if (pos < cap) dst[pos] = (unsigned short)j;
                    if (k==0){
                        int rp = atomicAdd(&g_rdeg[b_*NN + j], 1);
                        if (rp < MAXDEG_IN) g_rin[(size_t)(b_*NN+j)*MAXDEG_IN + rp] = (unsigned short)i_;
                    }
                }
                deg += __popc(bal);
            }
            if (lane==0){
                if (deg > cap) deg = cap;
                if (k==0) g_deg_adj[bn] = deg; else g_deg_a2[bn] = deg;
            }
        }
    }
    gridBarrier();

    // ================= graph layers =================
    for (int l=0; l<2; l++){
        // ---- zmean (block 0) + z projection (all blocks) ----
        if (bid == 0){
            float zm[BB];
            int h_ = tid>>6, e_ = tid&63;
            if (tid < 128){
                const float* W = attn_W + h_*EE*EE;
                #pragma unroll
                for (int b=0; b<BB; b++){
                    float acc = 0.f;
                    #pragma unroll 4
                    for (int d=0; d<EE; d++) acc += __ldcg(&g_hbar[b*EE+d])*W[d*EE+e_];
                    zm[b] = acc * (1.0f/(float)NN);
                }
            }
            __syncthreads();
            if (tid < 128){
                #pragma unroll
                for (int b=0; b<BB; b++) g_zmean[(h_*BB+b)*EE+e_] = zm[b];
            }
            if (tid < BB*EE) g_hbar[tid] = 0.f;
        }
        {
            float* sW = smf;         // 4096
            float* sh = smf+4096;    // 32*68
            for (int vb=bid; vb<256; vb+=GG){
                int h = vb>>7;
                int gn0 = (vb&127)*32;
                __syncthreads();
                const float* W = attn_W + h*EE*EE;
                for (int i=tid;i<EE*EE;i+=TT) sW[i] = W[i];
                for (int i=tid;i<32*EE;i+=TT) sh[(i>>6)*68+(i&63)] = __ldcg(&g_h[(size_t)gn0*EE + i]);
                __syncthreads();
                int eg = tid & 15;
                int ng = tid >> 4;
                int n0 = ng*2, n1 = ng*2+1;
                float4 acc0 = {0,0,0,0}, acc1 = {0,0,0,0};
                const float4* sW4 = (const float4*)sW;
                #pragma unroll 4
                for (int d=0; d<EE; d++){
                    float4 wv = sW4[d*16 + eg];
                    float h0 = sh[n0*68+d];
                    float h1 = sh[n1*68+d];
                    acc0.x += h0*wv.x; acc0.y += h0*wv.y; acc0.z += h0*wv.z; acc0.w += h0*wv.w;
                    acc1.x += h1*wv.x; acc1.y += h1*wv.y; acc1.z += h1*wv.z; acc1.w += h1*wv.w;
                }
                *(float4*)(g_zp + ((size_t)(gn0+n0))*2*EE + h*EE + eg*4) = acc0;
                *(float4*)(g_zp + ((size_t)(gn0+n1))*2*EE + h*EE + eg*4) = acc1;
                const float4* as4 = (const float4*)(a_src + h*EE);
                const float4* ad4 = (const float4*)(a_dst + h*EE);
                float4 as = as4[eg], ad = ad4[eg];
                float p0 = acc0.x*as.x + acc0.y*as.y + acc0.z*as.z + acc0.w*as.w;
                float q0 = acc0.x*ad.x + acc0.y*ad.y + acc0.z*ad.z + acc0.w*ad.w;
                float p1 = acc1.x*as.x + acc1.y*as.y + acc1.z*as.z + acc1.w*as.w;
                float q1 = acc1.x*ad.x + acc1.y*ad.y + acc1.z*ad.z + acc1.w*ad.w;
                #pragma unroll
                for (int o=8;o;o>>=1){
                    p0 += __shfl_down_sync(FULLMASK, p0, o, 16);
                    q0 += __shfl_down_sync(FULLMASK, q0, o, 16);
                    p1 += __shfl_down_sync(FULLMASK, p1, o, 16);
                    q1 += __shfl_down_sync(FULLMASK, q1, o, 16);
                }
                if (eg == 0){
                    g_ssrc[h*BB*NN + gn0 + n0] = p0;
                    g_sdst[h*BB*NN + gn0 + n0] = q0;
                    g_ssrc[h*BB*NN + gn0 + n1] = p1;
                    g_sdst[h*BB*NN + gn0 + n1] = q1;
                }
            }
        }
        gridBarrier();

        // ---- neighborhood attention aggregation ----
        {
            float* sacc = smf;               // 8*128
            float* sw0s = smf+1024;          // 8
            float* sw1s = smf+1032;          // 8
            int*   sjj  = (int*)(smf+1040);  // 8*32
            float* swts = smf+1296;          // 8*64
            for (int vb=bid; vb<BB*NN*KK; vb+=GG){
                int bn = vb>>1, k = vb&1;
                int b = bn>>11;
                int deg = (k==0) ? g_deg_adj[bn] : g_deg_a2[bn];
                if (deg == 0){
                    if (tid < EE){
                        float v = 0.5f*(__ldcg(&g_zmean[(0*BB+b)*EE+tid]) + __ldcg(&g_zmean[(1*BB+b)*EE+tid]));
                        g_aggs[((size_t)bn*KK + k)*EE + tid] = tanhf(v);
                    }
                } else {
                    const unsigned short* list = (k==0) ? (g_nbr_adj + (size_t)bn*MAXDEG_ADJ)
                                                        : (g_nbr_a2  + (size_t)bn*MAXDEG_A2);
                    float ssrc0 = __ldcg(&g_ssrc[bn]);
                    float ssrc1 = __ldcg(&g_ssrc[BB*NN + bn]);
                    const float* sd0 = g_sdst + b*NN;
                    const float* sd1 = g_sdst + BB*NN + b*NN;
                    const float* zb  = g_zp + (size_t)b*NN*2*EE;
                    float a0=0,a1=0,a2=0,a3=0,s0=0,s1=0;
                    const float* wrow = swts + w*64 + (lane>>4)*32;
                    int lane4 = lane*4;
                    for (int base = w*32; base < deg; base += 256){
                        int cnt = deg - base; if (cnt > 32) cnt = 32;
                        int jl = 0; float w0l = 0.f, w1l = 0.f;
                        if (lane < cnt){
                            jl = list[base + lane];
                            w0l = __expf(tanhf(ssrc0 + __ldcg(&sd0[jl])));
                            w1l = __expf(tanhf(ssrc1 + __ldcg(&sd1[jl])));
                        }
                        s0 += w0l; s1 += w1l;
                        sjj[w*32+lane] = jl;
                        swts[w*64+lane] = w0l;
                        swts[w*64+32+lane] = w1l;
                        __syncwarp();
                        if (cnt == 32){
                            #pragma unroll 8
                            for (int i=0;i<32;i++){
                                float wt = wrow[i];
                                float4 v = __ldcg((const float4*)(zb + (size_t)sjj[w*32+i]*2*EE + lane4));
                                a0 += wt*v.x; a1 += wt*v.y; a2 += wt*v.z; a3 += wt*v.w;
                            }
                        } else {
                            for (int i=0;i<cnt;i++){
                                float wt = wrow[i];
                                float4 v = __ldcg((const float4*)(zb + (size_t)sjj[w*32+i]*2*EE + lane4));
                                a0 += wt*v.x; a1 += wt*v.y; a2 += wt*v.z; a3 += wt*v.w;
                            }
                        }
                        __syncwarp();
                    }
                    s0 = warpSum(s0); s1 = warpSum(s1);
                    if (lane==0){ sw0s[w]=s0; sw1s[w]=s1; }
                    sacc[w*128+lane4+0]=a0; sacc[w*128+lane4+1]=a1;
                    sacc[w*128+lane4+2]=a2; sacc[w*128+lane4+3]=a3;
                    __syncthreads();
                    if (tid < EE){
                        float r0=0.f, r1=0.f, S0=0.f, S1=0.f;
                        #pragma unroll
                        for (int ww=0; ww<8; ww++){
                            r0 += sacc[ww*128+tid];
                            r1 += sacc[ww*128+64+tid];
                            S0 += sw0s[ww]; S1 += sw1s[ww];
                        }
                        float v = 0.5f*(r0/S0 + r1/S1);
                        g_aggs[((size_t)bn*KK + k)*EE + tid] = tanhf(v);
                    }
                }
                __syncthreads();
            }
        }
        gridBarrier();

        // ---- GRU update + hbar ----
        {
            float* sW  = smf;          // 64*192
            float* sU  = smf+12288;    // 64*192
            float* snxt= smf+24576;    // 8*64
            float* shh = smf+25088;    // 8*64
            float* srh = smf+25600;    // 8*64
            float* hacc= smf+26112;    // 64
            for (int i=tid;i<EE*192;i+=TT){ sW[i]=gru_W[i]; sU[i]=gru_U[i]; }
            __syncthreads();
            int e1 = lane, e2 = lane+32;
            for (int vb=bid; vb<BB*NN/16; vb+=GG){
                int b = vb>>7;
                float hs1 = 0.f, hs2 = 0.f;
                #pragma unroll
                for (int rep=0; rep<2; rep++){
                    int gn = vb*16 + w + rep*8;
                    const float* ag = g_aggs + (size_t)gn*KK*EE;
                    float a0_1 = __ldcg(&ag[e1]),    a0_2 = __ldcg(&ag[e2]);
                    float a1_1 = __ldcg(&ag[EE+e1]), a1_2 = __ldcg(&ag[EE+e2]);
                    float d0 = warpSum(a0_1*nbr_q[e1] + a0_2*nbr_q[e2]);
                    float d1 = warpSum(a1_1*nbr_q[e1] + a1_2*nbr_q[e2]);
                    float t0 = tanhf(d0), t1 = tanhf(d1);
                    float mx = fmaxf(t0,t1);
                    float ex0 = __expf(t0-mx), ex1 = __expf(t1-mx);
                    float inv = 1.0f/(ex0+ex1);
                    float c0 = ex0*inv, c1 = ex1*inv;
                    float nx1 = c0*a0_1 + c1*a1_1;
                    float nx2 = c0*a0_2 + c1*a1_2;
                    float h1 = __ldcg(&g_h[(size_t)gn*EE+e1]);
                    float h2 = __ldcg(&g_h[(size_t)gn*EE+e2]);
                    snxt[w*EE+e1]=nx1; snxt[w*EE+e2]=nx2;
                    shh [w*EE+e1]=h1;  shh [w*EE+e2]=h2;
                    __syncwarp();
                    float az1 = gru_b[e1],    az2 = gru_b[e2];
                    float ar1 = gru_b[64+e1], ar2 = gru_b[64+e2];
                    #pragma unroll
                    for (int d=0; d<EE; d++){
                        float nx = snxt[w*EE+d], hv = shh[w*EE+d];
                        az1 += nx*sW[d*192+e1]    + hv*sU[d*192+e1];
                        az2 += nx*sW[d*192+e2]    + hv*sU[d*192+e2];
                        ar1 += nx*sW[d*192+64+e1] + hv*sU[d*192+64+e1];
                        ar2 += nx*sW[d*192+64+e2] + hv*sU[d*192+64+e2];
                    }
                    float zg1 = sigmoidf_(az1), zg2 = sigmoidf_(az2);
                    float r1  = sigmoidf_(ar1), r2  = sigmoidf_(ar2);
                    srh[w*EE+e1] = r1*h1; srh[w*EE+e2] = r2*h2;
                    __syncwarp();
                    float at1 = gru_b[128+e1], at2 = gru_b[128+e2];
                    #pragma unroll
                    for (int d=0; d<EE; d++){
                        float nx = snxt[w*EE+d], rh = srh[w*EE+d];
                        at1 += nx*sW[d*192+128+e1] + rh*sU[d*192+128+e1];
                        at2 += nx*sW[d*192+128+e2] + rh*sU[d*192+128+e2];
                    }
                    float ht1 = tanhf(at1), ht2 = tanhf(at2);
                    float hn1 = (1.0f-zg1)*h1 + zg1*ht1;
                    float hn2 = (1.0f-zg2)*h2 + zg2*ht2;
                    g_h[(size_t)gn*EE+e1] = hn1;
                    g_h[(size_t)gn*EE+e2] = hn2;
                    hs1 += hn1; hs2 += hn2;
                }
                __syncthreads();
                if (tid < EE) hacc[tid] = 0.f;
                __syncthreads();
                atomicAdd(&hacc[e1], hs1);
                atomicAdd(&hacc[e2], hs2);
                __syncthreads();
                if (tid < EE) atomicAdd(&g_hbar[b*EE+tid], hacc[tid]);
            }
        }
        gridBarrier();
    }

    // ================= decoder + dual heads + gmax =================
    {
        float* sWd = smf;        // 4096
        float* sWu = smf+4096;   // 4096
        float* shh = smf+8192;   // 8*64
        for (int i=tid;i<EE*EE;i+=TT){ sWd[i]=dec_W0[i]; sWu[i]=dual_W0[i]; }
        __syncthreads();
        int e1 = lane, e2 = lane+32;
        for (int vb=bid; vb<BB*NN/16; vb+=GG){
            #pragma unroll
            for (int rep=0; rep<2; rep++){
                int gn = vb*16 + w + rep*8;
                float h1 = __ldcg(&g_h[(size_t)gn*EE+e1]);
                float h2 = __ldcg(&g_h[(size_t)gn*EE+e2]);
                shh[w*EE+e1]=h1; shh[w*EE+e2]=h2;
                __syncwarp();
                float t1 = dec_b0[e1], t2 = dec_b0[e2];
                #pragma unroll
                for (int d=0; d<EE; d++){ float hv=shh[w*EE+d]; t1 += hv*sWd[d*EE+e1]; t2 += hv*sWd[d*EE+e2]; }
                t1 = tanhf(t1); t2 = tanhf(t2);
                float p = warpSum(t1*dec_W1[e1] + t2*dec_W1[e2]);
                if (lane==0){
                    float nwv = p + dec_b1[0];
                    g_nw[gn] = nwv;
                    unsigned u = __float_as_uint(nwv);
                    u = (u & 0x80000000u) ? ~u : (u | 0x80000000u);
                    atomicMax(&g_gmaxu[gn>>11], u);
                }
                float u1 = dual_b0[e1], u2 = dual_b0[e2];
                #pragma unroll
                for (int d=0; d<EE; d++){ float hv=shh[w*EE+d]; u1 += hv*sWu[d*EE+e1]; u2 += hv*sWu[d*EE+e2]; }
                u1 = tanhf(u1); u2 = tanhf(u2);
                float q = warpSum(u1*dual_W1[e1] + u2*dual_W1[e2]);
                if (lane==0) g_dv[gn] = q + dual_b1[0];
                __syncwarp();
            }
        }
    }
    gridBarrier();

    // ================= softmax denominators =================
    {
        for (int vb=bid; vb<BB*NN/8; vb+=GG){
            int gn = vb*8 + w;
            int b = gn >> 11;
            unsigned u = __ldcg(&g_gmaxu[b]);
            float gm = __uint_as_float((u & 0x80000000u) ? (u ^ 0x80000000u) : ~u);
            int deg = g_deg_adj[gn];
            const unsigned short* list = g_nbr_adj + (size_t)gn*MAXDEG_ADJ;
            float s = 0.f;
            for (int t=lane; t<deg; t+=32) s += __expf(g_nw[b*NN + list[t]] - gm);
            s = warpSum(s);
            if (lane==0){
                g_Z[gn] = (deg>0) ? s : 1.0f;
                g_enw[gn] = __expf(g_nw[gn] - gm);
            }
        }
    }
    gridBarrier();

    // ================= MCF flow (blocks 0..BB-1) =================
    if (bid < BB){
        float* us = smf;   // 2048
        int b = bid;
        float s_[8], iZ[8], dm[8], en[8];
        int rd[8];
        #pragma unroll
        for (int i=0;i<8;i++){
            int gn = b*NN + i*TT + tid;
            iZ[i] = 1.0f/g_Z[gn];
            dm[i] = demands[gn];
            en[i] = g_enw[gn];
            rd[i] = min(g_rdeg[gn], MAXDEG_IN);
            s_[i] = 0.f;
        }
        for (int it=0; it<10; it++){
            #pragma unroll
            for (int i=0;i<8;i++) us[i*TT+tid] = s_[i]*iZ[i];
            __syncthreads();
            #pragma unroll
            for (int i=0;i<8;i++){
                const unsigned short* lst = g_rin + (size_t)(b*NN + i*TT + tid)*MAXDEG_IN;
                float a = 0.f;
                for (int t=0; t<rd[i]; t++) a += us[lst[t]];
                s_[i] = fmaxf(fmaf(en[i], a, -dm[i]), 0.f);
            }
            __syncthreads();
        }
        #pragma unroll
        for (int i=0;i<8;i++) g_s10[b*NN + i*TT + tid] = s_[i];
    }
    gridBarrier();

    // ================= flow cost + dual iterations + reduce =================
    {
        float* srf = smf;   // 8
        for (int vb=bid; vb<64; vb+=GG){
            int b = vb>>5;
            int nch = vb&31;
            float acc = 0.f;
            for (int idx = w; idx < 64; idx += 8){
                int n = nch*64 + idx;
                int gn = b*NN+n;
                int deg = g_deg_adj[gn];
                const unsigned short* list = g_nbr_adj + (size_t)gn*MAXDEG_ADJ;
                float si = g_s10[gn];
                float invZi = 1.0f/g_Z[gn];
                float dvi = g_dv[gn];
                float enwi = g_enw[gn];
                if (lane==0) acc += dvi * demands[gn];
                for (int t=lane; t<deg; t+=32){
                    int j = list[t];
                    int gj = b*NN+j;
                    float f = g_enw[gj]*invZi*si;
                    unsigned word = g_adjbit[(size_t)gj*(NN/32) + (n>>5)];
                    float ft = 0.f;
                    if ((word >> (n&31)) & 1u) ft = enwi * (g_s10[gj]/g_Z[gj]);
                    float fp = f - fminf(f, ft);
                    acc += fp*fp;
                    float dd = dvi - g_dv[gj];
                    float y = 0.f, m = 0.f;
                    #pragma unroll
                    for (int q=0; q<10; q++){
                        float gg = 2.0f*y - dd;
                        m = 0.9f*m + gg;
                        y = fmaxf(y - 0.1f*m, 0.f);
                    }
                    acc -= (y*y - dd*y);
                }
            }
            acc = warpSum(acc);
            if (lane==0) srf[w] = acc;
            __syncthreads();
            if (tid==0){
                float t_ = 0.f;
                #pragma unroll
                for (int i=0;i<8;i++) t_ += srf[i];
                atomicAdd(&out[b], t_);
            }
            __syncthreads();
        }
    }
}

// ---------------- launch ----------------
extern "C" void kernel_launch(void* const* d_in, const int* in_sizes, int n_in,
                              void* d_out, int out_size){
    const float* feat    = (const float*)d_in[0];
    const float* emb     = (const float*)d_in[1];
    const float* demands = (const float*)d_in[2];
    const float* neigh   = (const float*)d_in[4];
    const float* enc_W0  = (const float*)d_in[5];
    const float* enc_b0  = (const float*)d_in[6];
    const float* enc_W1  = (const float*)d_in[7];
    const float* enc_b1  = (const float*)d_in[8];
    const float* attn_W  = (const float*)d_in[9];
    const float* a_src   = (const float*)d_in[10];
    const float* a_dst   = (const float*)d_in[11];
    const float* nbr_q   = (const float*)d_in[12];
    const float* gru_W   = (const float*)d_in[13];
    const float* gru_U   = (const float*)d_in[14];
    const float* gru_b   = (const float*)d_in[15];
    const float* dec_W0  = (const float*)d_in[16];
    const float* dec_b0  = (const float*)d_in[17];
    const float* dec_W1  = (const float*)d_in[18];
    const float* dec_b1  = (const float*)d_in[19];
    const float* dual_W0 = (const float*)d_in[20];
    const float* dual_b0 = (const float*)d_in[21];
    const float* dual_W1 = (const float*)d_in[22];
    const float* dual_b1 = (const float*)d_in[23];
    float* out = (float*)d_out;

    static int configured = 0;
    if (!configured){
        cudaFuncSetAttribute(K_all, cudaFuncAttributeMaxDynamicSharedMemorySize, SMEM_FLOATS*4);
        configured = 1;
    }

    K_all<<<GG, TT, SMEM_FLOATS*4>>>(
        feat, emb, demands, neigh,
        enc_W0, enc_b0, enc_W1, enc_b1,
        attn_W, a_src, a_dst, nbr_q,
        gru_W, gru_U, gru_b,
        dec_W0, dec_b0, dec_W1, dec_b1,
        dual_W0, dual_b0, dual_W1, dual_b1,
        out);
}

// round 9
// speedup vs baseline: 2.0727x; 2.0727x over previous
#include <cuda_runtime.h>
#include <cuda_bf16.h>
#include <math.h>

#define BB 2
#define NN 2048
#define EE 64
#define HH 2
#define KK 2
#define FIN 18
#define MAXDEG_ADJ 64
#define MAXDEG_A2 512
#define MAXDEG_IN 64
#define FULLMASK 0xffffffffu

// ---------------- device scratch (static, no allocation) ----------------
__device__ float g_h[BB*NN*EE];
__device__ __align__(256) __nv_bfloat16 g_zb[BB*NN*2*EE];  // bf16 z, packed [h0 e0..63 | h1 e0..63]
__device__ float g_ssrc[HH*BB*NN];
__device__ float g_sdst[HH*BB*NN];
__device__ float g_hbar[2*BB*EE];          // layer-indexed h sums
__device__ float g_zmean[HH*BB*EE];
__device__ float g_aggs[BB*NN*KK*EE];
__device__ unsigned short g_nbr_adj[BB*NN*MAXDEG_ADJ];
__device__ unsigned short g_nbr_a2[BB*NN*MAXDEG_A2];
__device__ unsigned short g_rin[BB*NN*MAXDEG_IN];
__device__ int g_deg_adj[BB*NN];
__device__ int g_deg_a2[BB*NN];
__device__ int g_rdeg[BB*NN];
__device__ unsigned g_adjbit[BB*NN*(NN/32)];
__device__ float g_nw[BB*NN];
__device__ float g_dv[BB*NN];
__device__ float g_enw[BB*NN];
__device__ float g_Z[BB*NN];
__device__ float g_s10[BB*NN];
__device__ unsigned g_gmaxu[BB];

__device__ __forceinline__ float warpSum(float v){
    #pragma unroll
    for (int o=16;o;o>>=1) v += __shfl_xor_sync(FULLMASK, v, o);
    return v;
}
__device__ __forceinline__ float sigmoidf_(float x){ return 1.0f/(1.0f+__expf(-x)); }

// ---------------- zero output + counters ----------------
__global__ void K_zero(float* out){
    int idx = blockIdx.x*256 + threadIdx.x;
    if (idx < BB) out[idx] = 0.0f;
    if (idx < BB) g_gmaxu[idx] = 0u;
    if (idx < 2*BB*EE) g_hbar[idx] = 0.0f;
    if (idx < BB*NN) g_rdeg[idx] = 0;
}

// ---------------- encoder + hbar(buf0) ----------------
__global__ __launch_bounds__(256) void K_enc(const float* __restrict__ emb,
                                             const float* __restrict__ feat,
                                             const float* __restrict__ W0,
                                             const float* __restrict__ b0,
                                             const float* __restrict__ W1,
                                             const float* __restrict__ b1){
    __shared__ float sW0[FIN*EE];
    __shared__ float sW1[EE*EE];
    __shared__ float sx[4][FIN];
    __shared__ float st[4][EE];
    int tid = threadIdx.x;
    for (int i = tid; i < FIN*EE; i += 256) sW0[i] = W0[i];
    for (int i = tid; i < EE*EE;  i += 256) sW1[i] = W1[i];
    int g = tid >> 6, e = tid & 63;
    int gn = blockIdx.x*4 + g;
    if (e < 16)       sx[g][e]   = emb[gn*16 + e];
    else if (e < 18)  sx[g][e]   = feat[gn*2 + (e-16)];
    __syncthreads();
    float acc = b0[e];
    #pragma unroll
    for (int d=0; d<FIN; d++) acc += sx[g][d]*sW0[d*EE+e];
    st[g][e] = tanhf(acc);
    __syncthreads();
    float acc2 = b1[e];
    #pragma unroll
    for (int d=0; d<EE; d++) acc2 += st[g][d]*sW1[d*EE+e];
    float hv = tanhf(acc2);
    g_h[gn*EE+e] = hv;
    __syncthreads();
    st[g][e] = hv;
    __syncthreads();
    if (tid < EE){
        int b = blockIdx.x / (NN/4);
        atomicAdd(&g_hbar[b*EE+tid], st[0][tid]+st[1][tid]+st[2][tid]+st[3][tid]);
    }
}

// ---------------- CSR + bitset + reverse-CSR build ----------------
__global__ __launch_bounds__(256) void K_build(const float* __restrict__ neigh){
    int lane = threadIdx.x & 31;
    int row = blockIdx.x*8 + (threadIdx.x >> 5);
    int k  = row / (BB*NN);
    int bn = row % (BB*NN);
    int b_ = bn / NN, i_ = bn % NN;
    const float* src = neigh + (size_t)row * NN;
    unsigned short* dst = (k==0) ? (g_nbr_adj + (size_t)bn*MAXDEG_ADJ)
                                 : (g_nbr_a2  + (size_t)bn*MAXDEG_A2);
    int cap = (k==0) ? MAXDEG_ADJ : MAXDEG_A2;
    int deg = 0;
    #pragma unroll 4
    for (int c=0; c<NN/32; c++){
        int j = c*32 + lane;
        bool p = src[j] > 0.0f;
        unsigned bal = __ballot_sync(FULLMASK, p);
        if (k==0 && lane==0) g_adjbit[(size_t)bn*(NN/32) + c] = bal;
        int pre = __popc(bal & ((1u<<lane)-1u));
        if (p){
            int pos = deg + pre;
            if (pos < cap) dst[pos] = (unsigned short)j;
            if (k==0){
                int rp = atomicAdd(&g_rdeg[b_*NN + j], 1);
                if (rp < MAXDEG_IN) g_rin[(size_t)(b_*NN+j)*MAXDEG_IN + rp] = (unsigned short)i_;
            }
        }
        deg += __popc(bal);
    }
    if (lane==0){
        if (deg > cap) deg = cap;
        if (k==0) g_deg_adj[bn] = deg; else g_deg_a2[bn] = deg;
    }
}

// ---------------- z projection (bf16 out) + logits + fused zmean ----------
__global__ __launch_bounds__(256) void K_z(const float* __restrict__ attn_W,
                                           const float* __restrict__ a_src,
                                           const float* __restrict__ a_dst,
                                           int lay){
    int h = blockIdx.y;
    __shared__ __align__(16) float sW[EE*EE];
    __shared__ __align__(16) float sh[32][68];
    int tid = threadIdx.x;
    const float* W = attn_W + h*EE*EE;
    for (int i=tid;i<EE*EE;i+=256) sW[i] = W[i];
    int gn0 = blockIdx.x*32;
    for (int i=tid;i<32*EE;i+=256) sh[i>>6][i&63] = g_h[(size_t)gn0*EE + i];
    __syncthreads();
    int eg = tid & 15;
    int ng = tid >> 4;
    int n0 = ng*2, n1 = ng*2+1;
    float4 acc0 = {0,0,0,0}, acc1 = {0,0,0,0};
    const float4* sW4 = (const float4*)sW;
    #pragma unroll 4
    for (int d=0; d<EE; d++){
        float4 wv = sW4[d*16 + eg];
        float h0 = sh[n0][d];
        float h1 = sh[n1][d];
        acc0.x += h0*wv.x; acc0.y += h0*wv.y; acc0.z += h0*wv.z; acc0.w += h0*wv.w;
        acc1.x += h1*wv.x; acc1.y += h1*wv.y; acc1.z += h1*wv.z; acc1.w += h1*wv.w;
    }
    {
        __nv_bfloat162 b01 = __floats2bfloat162_rn(acc0.x, acc0.y);
        __nv_bfloat162 b23 = __floats2bfloat162_rn(acc0.z, acc0.w);
        uint2 u; u.x = *(unsigned*)&b01; u.y = *(unsigned*)&b23;
        *(uint2*)(g_zb + ((size_t)(gn0+n0))*2*EE + h*EE + eg*4) = u;
        b01 = __floats2bfloat162_rn(acc1.x, acc1.y);
        b23 = __floats2bfloat162_rn(acc1.z, acc1.w);
        u.x = *(unsigned*)&b01; u.y = *(unsigned*)&b23;
        *(uint2*)(g_zb + ((size_t)(gn0+n1))*2*EE + h*EE + eg*4) = u;
    }
    const float4* as4 = (const float4*)(a_src + h*EE);
    const float4* ad4 = (const float4*)(a_dst + h*EE);
    float4 as = as4[eg], ad = ad4[eg];
    float p0 = acc0.x*as.x + acc0.y*as.y + acc0.z*as.z + acc0.w*as.w;
    float q0 = acc0.x*ad.x + acc0.y*ad.y + acc0.z*ad.z + acc0.w*ad.w;
    float p1 = acc1.x*as.x + acc1.y*as.y + acc1.z*as.z + acc1.w*as.w;
    float q1 = acc1.x*ad.x + acc1.y*ad.y + acc1.z*ad.z + acc1.w*ad.w;
    #pragma unroll
    for (int o=8;o;o>>=1){
        p0 += __shfl_down_sync(FULLMASK, p0, o, 16);
        q0 += __shfl_down_sync(FULLMASK, q0, o, 16);
        p1 += __shfl_down_sync(FULLMASK, p1, o, 16);
        q1 += __shfl_down_sync(FULLMASK, q1, o, 16);
    }
    if (eg == 0){
        g_ssrc[h*BB*NN + gn0 + n0] = p0;
        g_sdst[h*BB*NN + gn0 + n0] = q0;
        g_ssrc[h*BB*NN + gn0 + n1] = p1;
        g_sdst[h*BB*NN + gn0 + n1] = q1;
    }
    // fused zmean: block 0 of each head computes zmean = (hbar/N) @ W
    if (blockIdx.x == 0 && tid < 128){
        int b = tid >> 6, e = tid & 63;
        const float* hb = g_hbar + lay*BB*EE + b*EE;
        float acc = 0.f;
        #pragma unroll 4
        for (int d=0; d<EE; d++) acc += hb[d]*sW[d*EE+e];
        g_zmean[(h*BB+b)*EE+e] = acc * (1.0f/(float)NN);
    }
}

// ---------------- neighborhood attention aggregation (bf16 gather) --------
__global__ __launch_bounds__(256) void K_agg(){
    int bn = blockIdx.x;
    int k  = blockIdx.y;
    int b  = bn >> 11;
    int tid = threadIdx.x, w = tid>>5, lane = tid&31;

    __shared__ float sacc[8][128];
    __shared__ float sw0s[8], sw1s[8];
    __shared__ int sj[8][32];
    __shared__ float swt[8][2][32];

    int deg = (k==0) ? g_deg_adj[bn] : g_deg_a2[bn];
    const unsigned short* list = (k==0) ? (g_nbr_adj + (size_t)bn*MAXDEG_ADJ)
                                        : (g_nbr_a2  + (size_t)bn*MAXDEG_A2);
    if (deg == 0){
        if (tid < EE){
            float v = 0.5f*(g_zmean[(0*BB+b)*EE+tid] + g_zmean[(1*BB+b)*EE+tid]);
            g_aggs[((size_t)bn*KK + k)*EE + tid] = tanhf(v);
        }
        return;
    }
    float ssrc0 = g_ssrc[bn];
    float ssrc1 = g_ssrc[BB*NN + bn];
    const float* sd0 = g_sdst + b*NN;
    const float* sd1 = g_sdst + BB*NN + b*NN;
    const __nv_bfloat16* zb = g_zb + (size_t)b*NN*2*EE;

    float a0=0.f, a1=0.f, a2=0.f, a3=0.f;
    float s0=0.f, s1=0.f;
    const float* wrow = swt[w][lane>>4];
    for (int base = w*32; base < deg; base += 256){
        int cnt = deg - base; if (cnt > 32) cnt = 32;
        int jl = 0; float w0l = 0.f, w1l = 0.f;
        if (lane < cnt){
            jl = list[base + lane];
            w0l = __expf(tanhf(ssrc0 + sd0[jl]));
            w1l = __expf(tanhf(ssrc1 + sd1[jl]));
        }
        s0 += w0l; s1 += w1l;
        sj[w][lane] = jl;
        swt[w][0][lane] = w0l;
        swt[w][1][lane] = w1l;
        __syncwarp();
        if (cnt == 32){
            #pragma unroll 8
            for (int i=0;i<32;i++){
                float wt = wrow[i];
                uint2 u = *(const uint2*)(zb + (size_t)sj[w][i]*2*EE + lane*4);
                __nv_bfloat162 lo = *reinterpret_cast<__nv_bfloat162*>(&u.x);
                __nv_bfloat162 hi = *reinterpret_cast<__nv_bfloat162*>(&u.y);
                float2 f01 = __bfloat1622float2(lo);
                float2 f23 = __bfloat1622float2(hi);
                a0 += wt*f01.x; a1 += wt*f01.y; a2 += wt*f23.x; a3 += wt*f23.y;
            }
        } else {
            for (int i=0;i<cnt;i++){
                float wt = wrow[i];
                uint2 u = *(const uint2*)(zb + (size_t)sj[w][i]*2*EE + lane*4);
                __nv_bfloat162 lo = *reinterpret_cast<__nv_bfloat162*>(&u.x);
                __nv_bfloat162 hi = *reinterpret_cast<__nv_bfloat162*>(&u.y);
                float2 f01 = __bfloat1622float2(lo);
                float2 f23 = __bfloat1622float2(hi);
                a0 += wt*f01.x; a1 += wt*f01.y; a2 += wt*f23.x; a3 += wt*f23.y;
            }
        }
        __syncwarp();
    }
    s0 = warpSum(s0); s1 = warpSum(s1);
    if (lane==0){ sw0s[w]=s0; sw1s[w]=s1; }
    sacc[w][lane*4+0]=a0; sacc[w][lane*4+1]=a1;
    sacc[w][lane*4+2]=a2; sacc[w][lane*4+3]=a3;
    __syncthreads();
    if (tid < EE){
        float r0=0.f, r1=0.f, S0=0.f, S1=0.f;
        #pragma unroll
        for (int ww=0; ww<8; ww++){
            r0 += sacc[ww][tid];
            r1 += sacc[ww][64+tid];
            S0 += sw0s[ww]; S1 += sw1s[ww];
        }
        float v = 0.5f*(r0/S0 + r1/S1);
        g_aggs[((size_t)bn*KK + k)*EE + tid] = tanhf(v);
    }
}

// ---------------- GRU update + hbar(buf1 on layer 0) ----------------------
__global__ __launch_bounds__(256) void K_gru(const float* __restrict__ nbr_q,
                                             const float* __restrict__ gru_W,
                                             const float* __restrict__ gru_U,
                                             const float* __restrict__ gru_b,
                                             int lay){
    extern __shared__ float dyn[];
    float* sW = dyn;              // 64*192
    float* sU = dyn + EE*192;     // 64*192
    __shared__ float snxt[8][EE];
    __shared__ float shh [8][EE];
    __shared__ float srh [8][EE];
    __shared__ float hacc[EE];
    int tid = threadIdx.x;
    for (int i=tid;i<EE*192;i+=256){ sW[i]=gru_W[i]; sU[i]=gru_U[i]; }
    if (tid < EE) hacc[tid] = 0.f;
    __syncthreads();
    int w = tid>>5, lane = tid&31;
    int e1 = lane, e2 = lane+32;
    float hs1 = 0.f, hs2 = 0.f;
    #pragma unroll
    for (int rep=0; rep<2; rep++){
        int gn = blockIdx.x*16 + w + rep*8;
        const float* ag = g_aggs + (size_t)gn*KK*EE;
        float a0_1 = ag[e1],      a0_2 = ag[e2];
        float a1_1 = ag[EE+e1],   a1_2 = ag[EE+e2];
        float d0 = warpSum(a0_1*nbr_q[e1] + a0_2*nbr_q[e2]);
        float d1 = warpSum(a1_1*nbr_q[e1] + a1_2*nbr_q[e2]);
        float t0 = tanhf(d0), t1 = tanhf(d1);
        float mx = fmaxf(t0,t1);
        float ex0 = __expf(t0-mx), ex1 = __expf(t1-mx);
        float inv = 1.0f/(ex0+ex1);
        float c0 = ex0*inv, c1 = ex1*inv;
        float nx1 = c0*a0_1 + c1*a1_1;
        float nx2 = c0*a0_2 + c1*a1_2;
        float h1 = g_h[(size_t)gn*EE+e1], h2 = g_h[(size_t)gn*EE+e2];
        snxt[w][e1]=nx1; snxt[w][e2]=nx2;
        shh [w][e1]=h1;  shh [w][e2]=h2;
        __syncwarp();
        float az1 = gru_b[e1],    az2 = gru_b[e2];
        float ar1 = gru_b[64+e1], ar2 = gru_b[64+e2];
        #pragma unroll
        for (int d=0; d<EE; d++){
            float nx = snxt[w][d], hv = shh[w][d];
            az1 += nx*sW[d*192+e1]    + hv*sU[d*192+e1];
            az2 += nx*sW[d*192+e2]    + hv*sU[d*192+e2];
            ar1 += nx*sW[d*192+64+e1] + hv*sU[d*192+64+e1];
            ar2 += nx*sW[d*192+64+e2] + hv*sU[d*192+64+e2];
        }
        float zg1 = sigmoidf_(az1), zg2 = sigmoidf_(az2);
        float r1  = sigmoidf_(ar1), r2  = sigmoidf_(ar2);
        srh[w][e1] = r1*h1; srh[w][e2] = r2*h2;
        __syncwarp();
        float at1 = gru_b[128+e1], at2 = gru_b[128+e2];
        #pragma unroll
        for (int d=0; d<EE; d++){
            float nx = snxt[w][d], rh = srh[w][d];
            at1 += nx*sW[d*192+128+e1] + rh*sU[d*192+128+e1];
            at2 += nx*sW[d*192+128+e2] + rh*sU[d*192+128+e2];
        }
        float ht1 = tanhf(at1), ht2 = tanhf(at2);
        float hn1 = (1.0f-zg1)*h1 + zg1*ht1;
        float hn2 = (1.0f-zg2)*h2 + zg2*ht2;
        g_h[(size_t)gn*EE+e1] = hn1;
        g_h[(size_t)gn*EE+e2] = hn2;
        hs1 += hn1; hs2 += hn2;
    }
    if (lay == 0){
        atomicAdd(&hacc[e1], hs1);
        atomicAdd(&hacc[e2], hs2);
        __syncthreads();
        if (tid < EE){
            int b = blockIdx.x / (NN/16);
            atomicAdd(&g_hbar[BB*EE + b*EE + tid], hacc[tid]);
        }
    }
}

// ---------------- decoder + dual heads + gmax ----------------
__global__ __launch_bounds__(256) void K_dec_dual(const float* __restrict__ dW0, const float* __restrict__ db0,
                                                  const float* __restrict__ dW1, const float* __restrict__ db1,
                                                  const float* __restrict__ uW0, const float* __restrict__ ub0,
                                                  const float* __restrict__ uW1, const float* __restrict__ ub1){
    __shared__ float sWd[EE*EE];
    __shared__ float sWu[EE*EE];
    __shared__ float shh[8][EE];
    int tid = threadIdx.x;
    for (int i=tid;i<EE*EE;i+=256){ sWd[i]=dW0[i]; sWu[i]=uW0[i]; }
    __syncthreads();
    int w = tid>>5, lane = tid&31;
    int e1 = lane, e2 = lane+32;
    #pragma unroll
    for (int rep=0; rep<2; rep++){
        int gn = blockIdx.x*16 + w + rep*8;
        float h1 = g_h[(size_t)gn*EE+e1], h2 = g_h[(size_t)gn*EE+e2];
        shh[w][e1]=h1; shh[w][e2]=h2;
        __syncwarp();
        float t1 = db0[e1], t2 = db0[e2];
        #pragma unroll
        for (int d=0; d<EE; d++){ float hv=shh[w][d]; t1 += hv*sWd[d*EE+e1]; t2 += hv*sWd[d*EE+e2]; }
        t1 = tanhf(t1); t2 = tanhf(t2);
        float p = warpSum(t1*dW1[e1] + t2*dW1[e2]);
        if (lane==0){
            float nwv = p + db1[0];
            g_nw[gn] = nwv;
            unsigned u = __float_as_uint(nwv);
            u = (u & 0x80000000u) ? ~u : (u | 0x80000000u);
            atomicMax(&g_gmaxu[gn>>11], u);
        }
        float u1 = ub0[e1], u2 = ub0[e2];
        #pragma unroll
        for (int d=0; d<EE; d++){ float hv=shh[w][d]; u1 += hv*sWu[d*EE+e1]; u2 += hv*sWu[d*EE+e2]; }
        u1 = tanhf(u1); u2 = tanhf(u2);
        float q = warpSum(u1*uW1[e1] + u2*uW1[e2]);
        if (lane==0) g_dv[gn] = q + ub1[0];
        __syncwarp();
    }
}

// ---------------- softmax denominators + exp(nw) ----------------
__global__ __launch_bounds__(256) void K_prop(){
    int w = threadIdx.x>>5, lane = threadIdx.x&31;
    int gn = blockIdx.x*8 + w;
    int b = gn >> 11;
    unsigned u = g_gmaxu[b];
    float gm = __uint_as_float((u & 0x80000000u) ? (u ^ 0x80000000u) : ~u);
    int deg = g_deg_adj[gn];
    const unsigned short* list = g_nbr_adj + (size_t)gn*MAXDEG_ADJ;
    float s = 0.f;
    for (int t=lane; t<deg; t+=32) s += __expf(g_nw[b*NN + list[t]] - gm);
    s = warpSum(s);
    if (lane==0){
        g_Z[gn] = (deg>0) ? s : 1.0f;
        g_enw[gn] = __expf(g_nw[gn] - gm);
    }
}

// ---------------- fused 10-iteration MCF, reverse-CSR gather --------------
__global__ __launch_bounds__(1024) void K_flow(const float* __restrict__ demands){
    int b = blockIdx.x;
    __shared__ float us[NN];
    int n1 = threadIdx.x, n2 = threadIdx.x + 1024;
    int gn1 = b*NN+n1, gn2 = b*NN+n2;
    float invZ1 = 1.0f/g_Z[gn1], invZ2 = 1.0f/g_Z[gn2];
    float d1 = demands[gn1], d2 = demands[gn2];
    float e1 = g_enw[gn1],  e2 = g_enw[gn2];
    int rd1 = min(g_rdeg[gn1], MAXDEG_IN);
    int rd2 = min(g_rdeg[gn2], MAXDEG_IN);
    const unsigned short* l1 = g_rin + (size_t)gn1*MAXDEG_IN;
    const unsigned short* l2 = g_rin + (size_t)gn2*MAXDEG_IN;
    float s1 = 0.f, s2 = 0.f;
    for (int it=0; it<10; it++){
        us[n1] = s1*invZ1; us[n2] = s2*invZ2;
        __syncthreads();
        float a1 = 0.f, a2 = 0.f;
        for (int t=0; t<rd1; t++) a1 += us[l1[t]];
        for (int t=0; t<rd2; t++) a2 += us[l2[t]];
        s1 = fmaxf(fmaf(e1, a1, -d1), 0.f);
        s2 = fmaxf(fmaf(e2, a2, -d2), 0.f);
        __syncthreads();
    }
    g_s10[gn1] = s1;
    g_s10[gn2] = s2;
}

// ---------------- flow cost + dual iterations + final reduction ----------
__global__ __launch_bounds__(256) void K_final(const float* __restrict__ demands,
                                               float* __restrict__ out){
    int b = blockIdx.y;
    int tid = threadIdx.x, w = tid>>5, lane = tid&31;
    float acc = 0.f;
    for (int idx = w; idx < 64; idx += 8){
        int n = blockIdx.x*64 + idx;
        int gn = b*NN+n;
        int deg = g_deg_adj[gn];
        const unsigned short* list = g_nbr_adj + (size_t)gn*MAXDEG_ADJ;
        float si = g_s10[gn];
        float invZi = 1.0f/g_Z[gn];
        float dvi = g_dv[gn];
        float enwi = g_enw[gn];
        if (lane==0) acc += dvi * demands[gn];
        for (int t=lane; t<deg; t+=32){
            int j = list[t];
            int gj = b*NN+j;
            float f = g_enw[gj]*invZi*si;
            unsigned word = g_adjbit[(size_t)gj*(NN/32) + (n>>5)];
            float ft = 0.f;
            if ((word >> (n&31)) & 1u) ft = enwi * (g_s10[gj]/g_Z[gj]);
            float fp = f - fminf(f, ft);
            acc += fp*fp;
            float dd = dvi - g_dv[gj];
            float y = 0.f, m = 0.f;
            #pragma unroll
            for (int q=0; q<10; q++){
                float gg = 2.0f*y - dd;
                m = 0.9f*m + gg;
                y = fmaxf(y - 0.1f*m, 0.f);
            }
            acc -= (y*y - dd*y);
        }
    }
    acc = warpSum(acc);
    __shared__ float sr[8];
    if (lane==0) sr[w] = acc;
    __syncthreads();
    if (tid==0){
        float t = 0.f; for (int i=0;i<8;i++) t += sr[i];
        atomicAdd(&out[b], t);
    }
}

// ---------------- launch ----------------
extern "C" void kernel_launch(void* const* d_in, const int* in_sizes, int n_in,
                              void* d_out, int out_size){
    const float* feat    = (const float*)d_in[0];
    const float* emb     = (const float*)d_in[1];
    const float* demands = (const float*)d_in[2];
    const float* neigh   = (const float*)d_in[4];
    const float* enc_W0  = (const float*)d_in[5];
    const float* enc_b0  = (const float*)d_in[6];
    const float* enc_W1  = (const float*)d_in[7];
    const float* enc_b1  = (const float*)d_in[8];
    const float* attn_W  = (const float*)d_in[9];
    const float* a_src   = (const float*)d_in[10];
    const float* a_dst   = (const float*)d_in[11];
    const float* nbr_q   = (const float*)d_in[12];
    const float* gru_W   = (const float*)d_in[13];
    const float* gru_U   = (const float*)d_in[14];
    const float* gru_b   = (const float*)d_in[15];
    const float* dec_W0  = (const float*)d_in[16];
    const float* dec_b0  = (const float*)d_in[17];
    const float* dec_W1  = (const float*)d_in[18];
    const float* dec_b1  = (const float*)d_in[19];
    const float* dual_W0 = (const float*)d_in[20];
    const float* dual_b0 = (const float*)d_in[21];
    const float* dual_W1 = (const float*)d_in[22];
    const float* dual_b1 = (const float*)d_in[23];
    float* out = (float*)d_out;

    static int configured = 0;
    if (!configured){
        cudaFuncSetAttribute(K_gru, cudaFuncAttributeMaxDynamicSharedMemorySize, 2*EE*192*4);
        configured = 1;
    }

    K_zero<<<(BB*NN+255)/256,256>>>(out);
    K_enc<<<BB*NN/4,256>>>(emb, feat, enc_W0, enc_b0, enc_W1, enc_b1);
    K_build<<<KK*BB*NN/8,256>>>(neigh);
    for (int l=0;l<2;l++){
        K_z<<<dim3(BB*NN/32,HH),256>>>(attn_W, a_src, a_dst, l);
        K_agg<<<dim3(BB*NN,KK),256>>>();
        K_gru<<<BB*NN/16,256, 2*EE*192*4>>>(nbr_q, gru_W, gru_U, gru_b, l);
    }
    K_dec_dual<<<BB*NN/16,256>>>(dec_W0,dec_b0,dec_W1,dec_b1,dual_W0,dual_b0,dual_W1,dual_b1);
    K_prop<<<BB*NN/8,256>>>();
    K_flow<<<BB,1024>>>(demands);
    K_final<<<dim3(NN/64,BB),256>>>(demands, out);
}

// round 11
// speedup vs baseline: 2.1698x; 1.0468x over previous
#include <cuda_runtime.h>
#include <cuda_bf16.h>
#include <math.h>

#define BB 2
#define NN 2048
#define EE 64
#define HH 2
#define KK 2
#define FIN 18
#define MAXDEG_ADJ 64
#define MAXDEG_A2 512
#define MAXDEG_IN 64
#define FULLMASK 0xffffffffu

// ---------------- device scratch (static, no allocation) ----------------
__device__ float g_h[BB*NN*EE];
__device__ __align__(256) __nv_bfloat16 g_zb[BB*NN*2*EE];  // bf16 z, packed [h0 e0..63 | h1 e0..63]
__device__ float g_ssrc[HH*BB*NN];
__device__ float g_sdst[HH*BB*NN];
__device__ float g_aggs[BB*NN*KK*EE];
__device__ unsigned short g_nbr_adj[BB*NN*MAXDEG_ADJ];
__device__ unsigned short g_nbr_a2[BB*NN*MAXDEG_A2];
__device__ unsigned short g_rin[BB*NN*MAXDEG_IN];
__device__ int g_deg_adj[BB*NN];
__device__ int g_deg_a2[BB*NN];
__device__ int g_rdeg[BB*NN];
__device__ unsigned g_adjbit[BB*NN*(NN/32)];
__device__ float g_nw[BB*NN];
__device__ float g_dv[BB*NN];
__device__ float g_enw[BB*NN];
__device__ float g_Z[BB*NN];
__device__ float g_s10[BB*NN];
__device__ unsigned g_gmaxu[BB];

__device__ __forceinline__ float warpSum(float v){
    #pragma unroll
    for (int o=16;o;o>>=1) v += __shfl_xor_sync(FULLMASK, v, o);
    return v;
}
__device__ __forceinline__ float sigmoidf_(float x){ return 1.0f/(1.0f+__expf(-x)); }

// ---------------- encoder (+ prelude zeroing of counters/out) -------------
__global__ __launch_bounds__(256) void K_enc(const float* __restrict__ emb,
                                             const float* __restrict__ feat,
                                             const float* __restrict__ W0,
                                             const float* __restrict__ b0,
                                             const float* __restrict__ W1,
                                             const float* __restrict__ b1,
                                             float* __restrict__ out){
    // prelude: zero rdeg (consumed by K_build, which runs after us), out, gmax
    int zidx = blockIdx.x*256 + threadIdx.x;
    if (zidx < BB*NN) g_rdeg[zidx] = 0;
    if (blockIdx.x == 0 && threadIdx.x < BB){ out[threadIdx.x] = 0.f; g_gmaxu[threadIdx.x] = 0u; }

    __shared__ float sW0[FIN*EE];
    __shared__ float sW1[EE*EE];
    __shared__ float sx[4][FIN];
    __shared__ float st[4][EE];
    int tid = threadIdx.x;
    for (int i = tid; i < FIN*EE; i += 256) sW0[i] = W0[i];
    for (int i = tid; i < EE*EE;  i += 256) sW1[i] = W1[i];
    int g = tid >> 6, e = tid & 63;
    int gn = blockIdx.x*4 + g;
    if (e < 16)       sx[g][e]   = emb[gn*16 + e];
    else if (e < 18)  sx[g][e]   = feat[gn*2 + (e-16)];
    __syncthreads();
    float acc = b0[e];
    #pragma unroll
    for (int d=0; d<FIN; d++) acc += sx[g][d]*sW0[d*EE+e];
    st[g][e] = tanhf(acc);
    __syncthreads();
    float acc2 = b1[e];
    #pragma unroll
    for (int d=0; d<EE; d++) acc2 += st[g][d]*sW1[d*EE+e];
    g_h[gn*EE+e] = tanhf(acc2);
}

// ---------------- CSR + bitset + reverse-CSR build ----------------
__global__ __launch_bounds__(256) void K_build(const float* __restrict__ neigh){
    int lane = threadIdx.x & 31;
    int row = blockIdx.x*8 + (threadIdx.x >> 5);
    int k  = row / (BB*NN);
    int bn = row % (BB*NN);
    int b_ = bn / NN, i_ = bn % NN;
    const float* src = neigh + (size_t)row * NN;
    unsigned short* dst = (k==0) ? (g_nbr_adj + (size_t)bn*MAXDEG_ADJ)
                                 : (g_nbr_a2  + (size_t)bn*MAXDEG_A2);
    int cap = (k==0) ? MAXDEG_ADJ : MAXDEG_A2;
    int deg = 0;
    #pragma unroll 4
    for (int c=0; c<NN/32; c++){
        int j = c*32 + lane;
        bool p = src[j] > 0.0f;
        unsigned bal = __ballot_sync(FULLMASK, p);
        if (k==0 && lane==0) g_adjbit[(size_t)bn*(NN/32) + c] = bal;
        int pre = __popc(bal & ((1u<<lane)-1u));
        if (p){
            int pos = deg + pre;
            if (pos < cap) dst[pos] = (unsigned short)j;
            if (k==0){
                int rp = atomicAdd(&g_rdeg[b_*NN + j], 1);
                if (rp < MAXDEG_IN) g_rin[(size_t)(b_*NN+j)*MAXDEG_IN + rp] = (unsigned short)i_;
            }
        }
        deg += __popc(bal);
    }
    if (lane==0){
        if (deg > cap) deg = cap;
        if (k==0) g_deg_adj[bn] = deg; else g_deg_a2[bn] = deg;
    }
}

// ---------------- z projection (bf16 out) + attention logits --------------
__global__ __launch_bounds__(256) void K_z(const float* __restrict__ attn_W,
                                           const float* __restrict__ a_src,
                                           const float* __restrict__ a_dst){
    int h = blockIdx.y;
    __shared__ __align__(16) float sW[EE*EE];
    __shared__ __align__(16) float sh[32][68];
    int tid = threadIdx.x;
    const float* W = attn_W + h*EE*EE;
    for (int i=tid;i<EE*EE;i+=256) sW[i] = W[i];
    int gn0 = blockIdx.x*32;
    for (int i=tid;i<32*EE;i+=256) sh[i>>6][i&63] = g_h[(size_t)gn0*EE + i];
    __syncthreads();
    int eg = tid & 15;
    int ng = tid >> 4;
    int n0 = ng*2, n1 = ng*2+1;
    float4 acc0 = {0,0,0,0}, acc1 = {0,0,0,0};
    const float4* sW4 = (const float4*)sW;
    #pragma unroll 4
    for (int d=0; d<EE; d++){
        float4 wv = sW4[d*16 + eg];
        float h0 = sh[n0][d];
        float h1 = sh[n1][d];
        acc0.x += h0*wv.x; acc0.y += h0*wv.y; acc0.z += h0*wv.z; acc0.w += h0*wv.w;
        acc1.x += h1*wv.x; acc1.y += h1*wv.y; acc1.z += h1*wv.z; acc1.w += h1*wv.w;
    }
    {
        __nv_bfloat162 b01 = __floats2bfloat162_rn(acc0.x, acc0.y);
        __nv_bfloat162 b23 = __floats2bfloat162_rn(acc0.z, acc0.w);
        uint2 u; u.x = *(unsigned*)&b01; u.y = *(unsigned*)&b23;
        *(uint2*)(g_zb + ((size_t)(gn0+n0))*2*EE + h*EE + eg*4) = u;
        b01 = __floats2bfloat162_rn(acc1.x, acc1.y);
        b23 = __floats2bfloat162_rn(acc1.z, acc1.w);
        u.x = *(unsigned*)&b01; u.y = *(unsigned*)&b23;
        *(uint2*)(g_zb + ((size_t)(gn0+n1))*2*EE + h*EE + eg*4) = u;
    }
    const float4* as4 = (const float4*)(a_src + h*EE);
    const float4* ad4 = (const float4*)(a_dst + h*EE);
    float4 as = as4[eg], ad = ad4[eg];
    float p0 = acc0.x*as.x + acc0.y*as.y + acc0.z*as.z + acc0.w*as.w;
    float q0 = acc0.x*ad.x + acc0.y*ad.y + acc0.z*ad.z + acc0.w*ad.w;
    float p1 = acc1.x*as.x + acc1.y*as.y + acc1.z*as.z + acc1.w*as.w;
    float q1 = acc1.x*ad.x + acc1.y*ad.y + acc1.z*ad.z + acc1.w*ad.w;
    #pragma unroll
    for (int o=8;o;o>>=1){
        p0 += __shfl_down_sync(FULLMASK, p0, o, 16);
        q0 += __shfl_down_sync(FULLMASK, q0, o, 16);
        p1 += __shfl_down_sync(FULLMASK, p1, o, 16);
        q1 += __shfl_down_sync(FULLMASK, q1, o, 16);
    }
    if (eg == 0){
        g_ssrc[h*BB*NN + gn0 + n0] = p0;
        g_sdst[h*BB*NN + gn0 + n0] = q0;
        g_ssrc[h*BB*NN + gn0 + n1] = p1;
        g_sdst[h*BB*NN + gn0 + n1] = q1;
    }
}

__device__ __forceinline__ void bf16row_acc(const __nv_bfloat16* row, int lane,
                                            float wt, float& a0, float& a1, float& a2, float& a3){
    uint2 u = *(const uint2*)(row + lane*4);
    __nv_bfloat162 lo = *reinterpret_cast<__nv_bfloat162*>(&u.x);
    __nv_bfloat162 hi = *reinterpret_cast<__nv_bfloat162*>(&u.y);
    float2 f01 = __bfloat1622float2(lo);
    float2 f23 = __bfloat1622float2(hi);
    a0 += wt*f01.x; a1 += wt*f01.y; a2 += wt*f23.x; a3 += wt*f23.y;
}

// ---------------- a2 (k=1) aggregation: block per node --------------------
__global__ __launch_bounds__(256) void K_agg_a2(){
    int bn = blockIdx.x;
    int b  = bn >> 11;
    int tid = threadIdx.x, w = tid>>5, lane = tid&31;

    __shared__ float sacc[8][128];
    __shared__ float sw0s[8], sw1s[8];
    __shared__ int sj[8][32];
    __shared__ float swt[8][2][32];

    int deg = g_deg_a2[bn];
    const unsigned short* list = g_nbr_a2 + (size_t)bn*MAXDEG_A2;
    const __nv_bfloat16* zb = g_zb + (size_t)b*NN*2*EE;

    float a0=0.f, a1=0.f, a2=0.f, a3=0.f;
    float s0=0.f, s1=0.f;
    if (deg == 0){
        // uniform attention over ALL nodes (softmax of all -BIG) — exact fallback
        for (int j = w*(NN/8); j < (w+1)*(NN/8); j++)
            bf16row_acc(zb + (size_t)j*2*EE, lane, 1.0f, a0,a1,a2,a3);
        if (lane == 0){ s0 = (float)(NN/8); s1 = (float)(NN/8); }
    } else {
        float ssrc0 = g_ssrc[bn];
        float ssrc1 = g_ssrc[BB*NN + bn];
        const float* sd0 = g_sdst + b*NN;
        const float* sd1 = g_sdst + BB*NN + b*NN;
        const float* wrow = swt[w][lane>>4];
        for (int base = w*32; base < deg; base += 256){
            int cnt = deg - base; if (cnt > 32) cnt = 32;
            int jl = 0; float w0l = 0.f, w1l = 0.f;
            if (lane < cnt){
                jl = list[base + lane];
                w0l = __expf(tanhf(ssrc0 + sd0[jl]));
                w1l = __expf(tanhf(ssrc1 + sd1[jl]));
            }
            s0 += w0l; s1 += w1l;
            sj[w][lane] = jl;
            swt[w][0][lane] = w0l;
            swt[w][1][lane] = w1l;
            __syncwarp();
            if (cnt == 32){
                #pragma unroll 8
                for (int i=0;i<32;i++)
                    bf16row_acc(zb + (size_t)sj[w][i]*2*EE, lane, wrow[i], a0,a1,a2,a3);
            } else {
                for (int i=0;i<cnt;i++)
                    bf16row_acc(zb + (size_t)sj[w][i]*2*EE, lane, wrow[i], a0,a1,a2,a3);
            }
            __syncwarp();
        }
    }
    s0 = warpSum(s0); s1 = warpSum(s1);
    if (lane==0){ sw0s[w]=s0; sw1s[w]=s1; }
    sacc[w][lane*4+0]=a0; sacc[w][lane*4+1]=a1;
    sacc[w][lane*4+2]=a2; sacc[w][lane*4+3]=a3;
    __syncthreads();
    if (tid < EE){
        float r0=0.f, r1=0.f, S0=0.f, S1=0.f;
        #pragma unroll
        for (int ww=0; ww<8; ww++){
            r0 += sacc[ww][tid];
            r1 += sacc[ww][64+tid];
            S0 += sw0s[ww]; S1 += sw1s[ww];
        }
        float v = 0.5f*(r0/S0 + r1/S1);
        g_aggs[((size_t)bn*KK + 1)*EE + tid] = tanhf(v);
    }
}

// ---------------- adj (k=0) aggregation: warp per node --------------------
__global__ __launch_bounds__(256) void K_agg_adj(){
    int w = threadIdx.x>>5, lane = threadIdx.x&31;
    int bn = blockIdx.x*8 + w;
    int b = bn >> 11;
    __shared__ int sj[8][32];
    __shared__ float sw0_[8][32], sw1_[8][32];
    int deg = g_deg_adj[bn];
    const __nv_bfloat16* zb = g_zb + (size_t)b*NN*2*EE;
    float a0=0,a1=0,a2=0,a3=0, ws0=0, ws1=0;
    if (deg==0){
        // uniform attention over ALL nodes — exact fallback (unreachable in practice)
        for (int j=0;j<NN;j++) bf16row_acc(zb + (size_t)j*2*EE, lane, 1.0f, a0,a1,a2,a3);
        ws0 = (float)NN; ws1 = (float)NN;
    } else {
        const unsigned short* list = g_nbr_adj + (size_t)bn*MAXDEG_ADJ;
        float ssrc0 = g_ssrc[bn], ssrc1 = g_ssrc[BB*NN+bn];
        const float* sd0 = g_sdst + b*NN;
        const float* sd1 = g_sdst + BB*NN + b*NN;
        const float* wrow = (lane<16) ? sw0_[w] : sw1_[w];
        for (int base=0; base<deg; base+=32){
            int cnt = deg - base; if (cnt>32) cnt=32;
            float w0 = 0.f, w1 = 0.f;
            if (lane < cnt){
                int j = list[base+lane];
                sj[w][lane] = j;
                w0 = __expf(tanhf(ssrc0 + sd0[j]));
                w1 = __expf(tanhf(ssrc1 + sd1[j]));
                sw0_[w][lane]=w0; sw1_[w][lane]=w1;
            }
            ws0 += w0; ws1 += w1;
            __syncwarp();
            #pragma unroll 8
            for (int i=0;i<cnt;i++)
                bf16row_acc(zb + (size_t)sj[w][i]*2*EE, lane, wrow[i], a0,a1,a2,a3);
            __syncwarp();
        }
        ws0 = warpSum(ws0); ws1 = warpSum(ws1);
    }
    float b0 = __shfl_down_sync(FULLMASK, a0, 16);
    float b1 = __shfl_down_sync(FULLMASK, a1, 16);
    float b2 = __shfl_down_sync(FULLMASK, a2, 16);
    float b3 = __shfl_down_sync(FULLMASK, a3, 16);
    if (lane < 16){
        float inv0 = 1.0f/ws0, inv1 = 1.0f/ws1;
        float4 o;
        o.x = tanhf(0.5f*(a0*inv0 + b0*inv1));
        o.y = tanhf(0.5f*(a1*inv0 + b1*inv1));
        o.z = tanhf(0.5f*(a2*inv0 + b2*inv1));
        o.w = tanhf(0.5f*(a3*inv0 + b3*inv1));
        *(float4*)(g_aggs + ((size_t)bn*KK+0)*EE + lane*4) = o;
    }
}

// ---------------- combine neighborhoods + GRU update ----------------------
__global__ __launch_bounds__(256) void K_gru(const float* __restrict__ nbr_q,
                                             const float* __restrict__ gru_W,
                                             const float* __restrict__ gru_U,
                                             const float* __restrict__ gru_b){
    extern __shared__ float dyn[];
    float* sW = dyn;              // 64*192
    float* sU = dyn + EE*192;     // 64*192
    __shared__ float snxt[8][EE];
    __shared__ float shh [8][EE];
    __shared__ float srh [8][EE];
    int tid = threadIdx.x;
    for (int i=tid;i<EE*192;i+=256){ sW[i]=gru_W[i]; sU[i]=gru_U[i]; }
    __syncthreads();
    int w = tid>>5, lane = tid&31;
    int e1 = lane, e2 = lane+32;
    #pragma unroll
    for (int rep=0; rep<2; rep++){
        int gn = blockIdx.x*16 + w + rep*8;
        const float* ag = g_aggs + (size_t)gn*KK*EE;
        float a0_1 = ag[e1],      a0_2 = ag[e2];
        float a1_1 = ag[EE+e1],   a1_2 = ag[EE+e2];
        float d0 = warpSum(a0_1*nbr_q[e1] + a0_2*nbr_q[e2]);
        float d1 = warpSum(a1_1*nbr_q[e1] + a1_2*nbr_q[e2]);
        float t0 = tanhf(d0), t1 = tanhf(d1);
        float mx = fmaxf(t0,t1);
        float ex0 = __expf(t0-mx), ex1 = __expf(t1-mx);
        float inv = 1.0f/(ex0+ex1);
        float c0 = ex0*inv, c1 = ex1*inv;
        float nx1 = c0*a0_1 + c1*a1_1;
        float nx2 = c0*a0_2 + c1*a1_2;
        float h1 = g_h[(size_t)gn*EE+e1], h2 = g_h[(size_t)gn*EE+e2];
        snxt[w][e1]=nx1; snxt[w][e2]=nx2;
        shh [w][e1]=h1;  shh [w][e2]=h2;
        __syncwarp();
        float az1 = gru_b[e1],    az2 = gru_b[e2];
        float ar1 = gru_b[64+e1], ar2 = gru_b[64+e2];
        #pragma unroll
        for (int d=0; d<EE; d++){
            float nx = snxt[w][d], hv = shh[w][d];
            az1 += nx*sW[d*192+e1]    + hv*sU[d*192+e1];
            az2 += nx*sW[d*192+e2]    + hv*sU[d*192+e2];
            ar1 += nx*sW[d*192+64+e1] + hv*sU[d*192+64+e1];
            ar2 += nx*sW[d*192+64+e2] + hv*sU[d*192+64+e2];
        }
        float zg1 = sigmoidf_(az1), zg2 = sigmoidf_(az2);
        float r1  = sigmoidf_(ar1), r2  = sigmoidf_(ar2);
        srh[w][e1] = r1*h1; srh[w][e2] = r2*h2;
        __syncwarp();
        float at1 = gru_b[128+e1], at2 = gru_b[128+e2];
        #pragma unroll
        for (int d=0; d<EE; d++){
            float nx = snxt[w][d], rh = srh[w][d];
            at1 += nx*sW[d*192+128+e1] + rh*sU[d*192+128+e1];
            at2 += nx*sW[d*192+128+e2] + rh*sU[d*192+128+e2];
        }
        float ht1 = tanhf(at1), ht2 = tanhf(at2);
        g_h[(size_t)gn*EE+e1] = (1.0f-zg1)*h1 + zg1*ht1;
        g_h[(size_t)gn*EE+e2] = (1.0f-zg2)*h2 + zg2*ht2;
    }
}

// ---------------- decoder + dual heads + gmax ----------------
__global__ __launch_bounds__(256) void K_dec_dual(const float* __restrict__ dW0, const float* __restrict__ db0,
                                                  const float* __restrict__ dW1, const float* __restrict__ db1,
                                                  const float* __restrict__ uW0, const float* __restrict__ ub0,
                                                  const float* __restrict__ uW1, const float* __restrict__ ub1){
    __shared__ float sWd[EE*EE];
    __shared__ float sWu[EE*EE];
    __shared__ float shh[8][EE];
    int tid = threadIdx.x;
    for (int i=tid;i<EE*EE;i+=256){ sWd[i]=dW0[i]; sWu[i]=uW0[i]; }
    __syncthreads();
    int w = tid>>5, lane = tid&31;
    int e1 = lane, e2 = lane+32;
    #pragma unroll
    for (int rep=0; rep<2; rep++){
        int gn = blockIdx.x*16 + w + rep*8;
        float h1 = g_h[(size_t)gn*EE+e1], h2 = g_h[(size_t)gn*EE+e2];
        shh[w][e1]=h1; shh[w][e2]=h2;
        __syncwarp();
        float t1 = db0[e1], t2 = db0[e2];
        #pragma unroll
        for (int d=0; d<EE; d++){ float hv=shh[w][d]; t1 += hv*sWd[d*EE+e1]; t2 += hv*sWd[d*EE+e2]; }
        t1 = tanhf(t1); t2 = tanhf(t2);
        float p = warpSum(t1*dW1[e1] + t2*dW1[e2]);
        if (lane==0){
            float nwv = p + db1[0];
            g_nw[gn] = nwv;
            unsigned u = __float_as_uint(nwv);
            u = (u & 0x80000000u) ? ~u : (u | 0x80000000u);
            atomicMax(&g_gmaxu[gn>>11], u);
        }
        float u1 = ub0[e1], u2 = ub0[e2];
        #pragma unroll
        for (int d=0; d<EE; d++){ float hv=shh[w][d]; u1 += hv*sWu[d*EE+e1]; u2 += hv*sWu[d*EE+e2]; }
        u1 = tanhf(u1); u2 = tanhf(u2);
        float q = warpSum(u1*uW1[e1] + u2*uW1[e2]);
        if (lane==0) g_dv[gn] = q + ub1[0];
        __syncwarp();
    }
}

// ---------------- softmax denominators + exp(nw) ----------------
__global__ __launch_bounds__(256) void K_prop(){
    int w = threadIdx.x>>5, lane = threadIdx.x&31;
    int gn = blockIdx.x*8 + w;
    int b = gn >> 11;
    unsigned u = g_gmaxu[b];
    float gm = __uint_as_float((u & 0x80000000u) ? (u ^ 0x80000000u) : ~u);
    int deg = g_deg_adj[gn];
    const unsigned short* list = g_nbr_adj + (size_t)gn*MAXDEG_ADJ;
    float s = 0.f;
    for (int t=lane; t<deg; t+=32) s += __expf(g_nw[b*NN + list[t]] - gm);
    s = warpSum(s);
    if (lane==0){
        g_Z[gn] = (deg>0) ? s : 1.0f;
        g_enw[gn] = __expf(g_nw[gn] - gm);
    }
}

// ---------------- fused 10-iteration MCF, reverse-CSR gather --------------
__global__ __launch_bounds__(1024) void K_flow(const float* __restrict__ demands){
    int b = blockIdx.x;
    __shared__ float us[NN];
    int n1 = threadIdx.x, n2 = threadIdx.x + 1024;
    int gn1 = b*NN+n1, gn2 = b*NN+n2;
    float invZ1 = 1.0f/g_Z[gn1], invZ2 = 1.0f/g_Z[gn2];
    float d1 = demands[gn1], d2 = demands[gn2];
    float e1 = g_enw[gn1],  e2 = g_enw[gn2];
    int rd1 = min(g_rdeg[gn1], MAXDEG_IN);
    int rd2 = min(g_rdeg[gn2], MAXDEG_IN);
    const unsigned short* l1 = g_rin + (size_t)gn1*MAXDEG_IN;
    const unsigned short* l2 = g_rin + (size_t)gn2*MAXDEG_IN;
    float s1 = 0.f, s2 = 0.f;
    for (int it=0; it<10; it++){
        us[n1] = s1*invZ1; us[n2] = s2*invZ2;
        __syncthreads();
        float a1 = 0.f, a2 = 0.f;
        for (int t=0; t<rd1; t++) a1 += us[l1[t]];
        for (int t=0; t<rd2; t++) a2 += us[l2[t]];
        s1 = fmaxf(fmaf(e1, a1, -d1), 0.f);
        s2 = fmaxf(fmaf(e2, a2, -d2), 0.f);
        __syncthreads();
    }
    g_s10[gn1] = s1;
    g_s10[gn2] = s2;
}

// ---------------- flow cost + dual iterations + final reduction ----------
__global__ __launch_bounds__(256) void K_final(const float* __restrict__ demands,
                                               float* __restrict__ out){
    int b = blockIdx.y;
    int tid = threadIdx.x, w = tid>>5, lane = tid&31;
    float acc = 0.f;
    for (int idx = w; idx < 64; idx += 8){
        int n = blockIdx.x*64 + idx;
        int gn = b*NN+n;
        int deg = g_deg_adj[gn];
        const unsigned short* list = g_nbr_adj + (size_t)gn*MAXDEG_ADJ;
        float si = g_s10[gn];
        float invZi = 1.0f/g_Z[gn];
        float dvi = g_dv[gn];
        float enwi = g_enw[gn];
        if (lane==0) acc += dvi * demands[gn];
        for (int t=lane; t<deg; t+=32){
            int j = list[t];
            int gj = b*NN+j;
            float f = g_enw[gj]*invZi*si;
            unsigned word = g_adjbit[(size_t)gj*(NN/32) + (n>>5)];
            float ft = 0.f;
            if ((word >> (n&31)) & 1u) ft = enwi * (g_s10[gj]/g_Z[gj]);
            float fp = f - fminf(f, ft);
            acc += fp*fp;
            float dd = dvi - g_dv[gj];
            float y = 0.f, m = 0.f;
            #pragma unroll
            for (int q=0; q<10; q++){
                float gg = 2.0f*y - dd;
                m = 0.9f*m + gg;
                y = fmaxf(y - 0.1f*m, 0.f);
            }
            acc -= (y*y - dd*y);
        }
    }
    acc = warpSum(acc);
    __shared__ float sr[8];
    if (lane==0) sr[w] = acc;
    __syncthreads();
    if (tid==0){
        float t = 0.f; for (int i=0;i<8;i++) t += sr[i];
        atomicAdd(&out[b], t);
    }
}

// ---------------- launch ----------------
extern "C" void kernel_launch(void* const* d_in, const int* in_sizes, int n_in,
                              void* d_out, int out_size){
    const float* feat    = (const float*)d_in[0];
    const float* emb     = (const float*)d_in[1];
    const float* demands = (const float*)d_in[2];
    const float* neigh   = (const float*)d_in[4];
    const float* enc_W0  = (const float*)d_in[5];
    const float* enc_b0  = (const float*)d_in[6];
    const float* enc_W1  = (const float*)d_in[7];
    const float* enc_b1  = (const float*)d_in[8];
    const float* attn_W  = (const float*)d_in[9];
    const float* a_src   = (const float*)d_in[10];
    const float* a_dst   = (const float*)d_in[11];
    const float* nbr_q   = (const float*)d_in[12];
    const float* gru_W   = (const float*)d_in[13];
    const float* gru_U   = (const float*)d_in[14];
    const float* gru_b   = (const float*)d_in[15];
    const float* dec_W0  = (const float*)d_in[16];
    const float* dec_b0  = (const float*)d_in[17];
    const float* dec_W1  = (const float*)d_in[18];
    const float* dec_b1  = (const float*)d_in[19];
    const float* dual_W0 = (const float*)d_in[20];
    const float* dual_b0 = (const float*)d_in[21];
    const float* dual_W1 = (const float*)d_in[22];
    const float* dual_b1 = (const float*)d_in[23];
    float* out = (float*)d_out;

    static int configured = 0;
    if (!configured){
        cudaFuncSetAttribute(K_gru, cudaFuncAttributeMaxDynamicSharedMemorySize, 2*EE*192*4);
        configured = 1;
    }

    // NOTE: ncu window captures the 4th launch -> K_agg_a2 (layer 0)
    K_enc<<<BB*NN/4,256>>>(emb, feat, enc_W0, enc_b0, enc_W1, enc_b1, out);
    K_build<<<KK*BB*NN/8,256>>>(neigh);
    for (int l=0;l<2;l++){
        K_z<<<dim3(BB*NN/32,HH),256>>>(attn_W, a_src, a_dst);
        K_agg_a2<<<BB*NN,256>>>();
        K_agg_adj<<<BB*NN/8,256>>>();
        K_gru<<<BB*NN/16,256, 2*EE*192*4>>>(nbr_q, gru_W, gru_U, gru_b);
    }
    K_dec_dual<<<BB*NN/16,256>>>(dec_W0,dec_b0,dec_W1,dec_b1,dual_W0,dual_b0,dual_W1,dual_b1);
    K_prop<<<BB*NN/8,256>>>();
    K_flow<<<BB,1024>>>(demands);
    K_final<<<dim3(NN/64,BB),256>>>(demands, out);
}

// round 12
// speedup vs baseline: 2.2258x; 1.0258x over previous
#include <cuda_runtime.h>
#include <cuda_bf16.h>
#include <math.h>

#define BB 2
#define NN 2048
#define EE 64
#define HH 2
#define KK 2
#define FIN 18
#define MAXDEG_ADJ 64
#define MAXDEG_A2 512
#define MAXDEG_IN 64
#define FULLMASK 0xffffffffu

// ---------------- device scratch (static, no allocation) ----------------
__device__ float g_h[BB*NN*EE];
__device__ __align__(256) __nv_bfloat16 g_zb[BB*NN*2*EE];  // bf16 z, packed [h0 e0..63 | h1 e0..63]
__device__ float g_ssrc[HH*BB*NN];
__device__ float g_sdst[HH*BB*NN];
__device__ float g_aggs[BB*NN*KK*EE];
__device__ unsigned short g_nbr_adj[BB*NN*MAXDEG_ADJ];
__device__ unsigned short g_nbr_a2[BB*NN*MAXDEG_A2];
__device__ unsigned short g_rin[BB*NN*MAXDEG_IN];
__device__ int g_deg_adj[BB*NN];
__device__ int g_deg_a2[BB*NN];
__device__ int g_rdeg[BB*NN];
__device__ unsigned g_adjbit[BB*NN*(NN/32)];
__device__ float g_nw[BB*NN];
__device__ float g_dv[BB*NN];
__device__ float g_enw[BB*NN];
__device__ float g_Z[BB*NN];
__device__ float g_s10[BB*NN];
__device__ unsigned g_gmaxu[BB];

__device__ __forceinline__ float warpSum(float v){
    #pragma unroll
    for (int o=16;o;o>>=1) v += __shfl_xor_sync(FULLMASK, v, o);
    return v;
}
__device__ __forceinline__ float sigmoidf_(float x){ return 1.0f/(1.0f+__expf(-x)); }

// ---------------- encoder (+ prelude zeroing of counters/out) -------------
__global__ __launch_bounds__(256) void K_enc(const float* __restrict__ emb,
                                             const float* __restrict__ feat,
                                             const float* __restrict__ W0,
                                             const float* __restrict__ b0,
                                             const float* __restrict__ W1,
                                             const float* __restrict__ b1,
                                             float* __restrict__ out){
    int zidx = blockIdx.x*256 + threadIdx.x;
    if (zidx < BB*NN) g_rdeg[zidx] = 0;
    if (blockIdx.x == 0 && threadIdx.x < BB){ out[threadIdx.x] = 0.f; g_gmaxu[threadIdx.x] = 0u; }

    __shared__ float sW0[FIN*EE];
    __shared__ float sW1[EE*EE];
    __shared__ float sx[4][FIN];
    __shared__ float st[4][EE];
    int tid = threadIdx.x;
    for (int i = tid; i < FIN*EE; i += 256) sW0[i] = W0[i];
    for (int i = tid; i < EE*EE;  i += 256) sW1[i] = W1[i];
    int g = tid >> 6, e = tid & 63;
    int gn = blockIdx.x*4 + g;
    if (e < 16)       sx[g][e]   = emb[gn*16 + e];
    else if (e < 18)  sx[g][e]   = feat[gn*2 + (e-16)];
    __syncthreads();
    float acc = b0[e];
    #pragma unroll
    for (int d=0; d<FIN; d++) acc += sx[g][d]*sW0[d*EE+e];
    st[g][e] = tanhf(acc);
    __syncthreads();
    float acc2 = b1[e];
    #pragma unroll
    for (int d=0; d<EE; d++) acc2 += st[g][d]*sW1[d*EE+e];
    g_h[gn*EE+e] = tanhf(acc2);
}

// ---------------- CSR + bitset + reverse-CSR build ----------------
__global__ __launch_bounds__(256) void K_build(const float* __restrict__ neigh){
    int lane = threadIdx.x & 31;
    int row = blockIdx.x*8 + (threadIdx.x >> 5);
    int k  = row / (BB*NN);
    int bn = row % (BB*NN);
    int b_ = bn / NN, i_ = bn % NN;
    const float* src = neigh + (size_t)row * NN;
    unsigned short* dst = (k==0) ? (g_nbr_adj + (size_t)bn*MAXDEG_ADJ)
                                 : (g_nbr_a2  + (size_t)bn*MAXDEG_A2);
    int cap = (k==0) ? MAXDEG_ADJ : MAXDEG_A2;
    int deg = 0;
    #pragma unroll 4
    for (int c=0; c<NN/32; c++){
        int j = c*32 + lane;
        bool p = src[j] > 0.0f;
        unsigned bal = __ballot_sync(FULLMASK, p);
        if (k==0 && lane==0) g_adjbit[(size_t)bn*(NN/32) + c] = bal;
        int pre = __popc(bal & ((1u<<lane)-1u));
        if (p){
            int pos = deg + pre;
            if (pos < cap) dst[pos] = (unsigned short)j;
            if (k==0){
                int rp = atomicAdd(&g_rdeg[b_*NN + j], 1);
                if (rp < MAXDEG_IN) g_rin[(size_t)(b_*NN+j)*MAXDEG_IN + rp] = (unsigned short)i_;
            }
        }
        deg += __popc(bal);
    }
    if (lane==0){
        if (deg > cap) deg = cap;
        if (k==0) g_deg_adj[bn] = deg; else g_deg_a2[bn] = deg;
    }
}

// ---------------- z projection (bf16 out) + attention logits --------------
__global__ __launch_bounds__(256) void K_z(const float* __restrict__ attn_W,
                                           const float* __restrict__ a_src,
                                           const float* __restrict__ a_dst){
    int h = blockIdx.y;
    __shared__ __align__(16) float sW[EE*EE];
    __shared__ __align__(16) float sh[32][68];
    int tid = threadIdx.x;
    const float* W = attn_W + h*EE*EE;
    for (int i=tid;i<EE*EE;i+=256) sW[i] = W[i];
    int gn0 = blockIdx.x*32;
    for (int i=tid;i<32*EE;i+=256) sh[i>>6][i&63] = g_h[(size_t)gn0*EE + i];
    __syncthreads();
    int eg = tid & 15;
    int ng = tid >> 4;
    int n0 = ng*2, n1 = ng*2+1;
    float4 acc0 = {0,0,0,0}, acc1 = {0,0,0,0};
    const float4* sW4 = (const float4*)sW;
    #pragma unroll 4
    for (int d=0; d<EE; d++){
        float4 wv = sW4[d*16 + eg];
        float h0 = sh[n0][d];
        float h1 = sh[n1][d];
        acc0.x += h0*wv.x; acc0.y += h0*wv.y; acc0.z += h0*wv.z; acc0.w += h0*wv.w;
        acc1.x += h1*wv.x; acc1.y += h1*wv.y; acc1.z += h1*wv.z; acc1.w += h1*wv.w;
    }
    {
        __nv_bfloat162 b01 = __floats2bfloat162_rn(acc0.x, acc0.y);
        __nv_bfloat162 b23 = __floats2bfloat162_rn(acc0.z, acc0.w);
        uint2 u; u.x = *(unsigned*)&b01; u.y = *(unsigned*)&b23;
        *(uint2*)(g_zb + ((size_t)(gn0+n0))*2*EE + h*EE + eg*4) = u;
        b01 = __floats2bfloat162_rn(acc1.x, acc1.y);
        b23 = __floats2bfloat162_rn(acc1.z, acc1.w);
        u.x = *(unsigned*)&b01; u.y = *(unsigned*)&b23;
        *(uint2*)(g_zb + ((size_t)(gn0+n1))*2*EE + h*EE + eg*4) = u;
    }
    const float4* as4 = (const float4*)(a_src + h*EE);
    const float4* ad4 = (const float4*)(a_dst + h*EE);
    float4 as = as4[eg], ad = ad4[eg];
    float p0 = acc0.x*as.x + acc0.y*as.y + acc0.z*as.z + acc0.w*as.w;
    float q0 = acc0.x*ad.x + acc0.y*ad.y + acc0.z*ad.z + acc0.w*ad.w;
    float p1 = acc1.x*as.x + acc1.y*as.y + acc1.z*as.z + acc1.w*as.w;
    float q1 = acc1.x*ad.x + acc1.y*ad.y + acc1.z*ad.z + acc1.w*ad.w;
    #pragma unroll
    for (int o=8;o;o>>=1){
        p0 += __shfl_down_sync(FULLMASK, p0, o, 16);
        q0 += __shfl_down_sync(FULLMASK, q0, o, 16);
        p1 += __shfl_down_sync(FULLMASK, p1, o, 16);
        q1 += __shfl_down_sync(FULLMASK, q1, o, 16);
    }
    if (eg == 0){
        g_ssrc[h*BB*NN + gn0 + n0] = p0;
        g_sdst[h*BB*NN + gn0 + n0] = q0;
        g_ssrc[h*BB*NN + gn0 + n1] = p1;
        g_sdst[h*BB*NN + gn0 + n1] = q1;
    }
}

__device__ __forceinline__ void bf16off_acc(const __nv_bfloat16* base, int off, int lane4,
                                            float wt, float& a0, float& a1, float& a2, float& a3){
    uint2 u = *(const uint2*)(base + off + lane4);
    __nv_bfloat162 lo = *reinterpret_cast<__nv_bfloat162*>(&u.x);
    __nv_bfloat162 hi = *reinterpret_cast<__nv_bfloat162*>(&u.y);
    float2 f01 = __bfloat1622float2(lo);
    float2 f23 = __bfloat1622float2(hi);
    a0 += wt*f01.x; a1 += wt*f01.y; a2 += wt*f23.x; a3 += wt*f23.y;
}

// ---------------- a2 (k=1) aggregation: block per node --------------------
__global__ __launch_bounds__(256) void K_agg_a2(){
    int bn = blockIdx.x;
    int b  = bn >> 11;
    int tid = threadIdx.x, w = tid>>5, lane = tid&31;

    __shared__ float sacc[8][128];
    __shared__ float sw0s[8], sw1s[8];
    __shared__ int sj[8][32];          // pre-scaled element offsets (j*128)
    __shared__ float swt[8][2][32];

    int deg = g_deg_a2[bn];
    const unsigned short* list = g_nbr_a2 + (size_t)bn*MAXDEG_A2;
    const __nv_bfloat16* zb = g_zb + (size_t)b*NN*2*EE;

    float a0=0.f, a1=0.f, a2=0.f, a3=0.f;
    float s0=0.f, s1=0.f;
    int lane4 = lane*4;
    if (deg == 0){
        for (int j = w*(NN/8); j < (w+1)*(NN/8); j++)
            bf16off_acc(zb, j*128, lane4, 1.0f, a0,a1,a2,a3);
        if (lane == 0){ s0 = (float)(NN/8); s1 = (float)(NN/8); }
    } else {
        float ssrc0 = g_ssrc[bn];
        float ssrc1 = g_ssrc[BB*NN + bn];
        const float* sd0 = g_sdst + b*NN;
        const float* sd1 = g_sdst + BB*NN + b*NN;
        const float* wrow = swt[w][lane>>4];
        for (int base = w*32; base < deg; base += 256){
            int cnt = deg - base; if (cnt > 32) cnt = 32;
            int jl = 0; float w0l = 0.f, w1l = 0.f;
            if (lane < cnt){
                jl = list[base + lane];
                w0l = __expf(tanhf(ssrc0 + sd0[jl]));
                w1l = __expf(tanhf(ssrc1 + sd1[jl]));
            }
            s0 += w0l; s1 += w1l;
            sj[w][lane] = jl*128;
            swt[w][0][lane] = w0l;
            swt[w][1][lane] = w1l;
            __syncwarp();
            if (cnt == 32){
                #pragma unroll 8
                for (int i=0;i<32;i++)
                    bf16off_acc(zb, sj[w][i], lane4, wrow[i], a0,a1,a2,a3);
            } else {
                for (int i=0;i<cnt;i++)
                    bf16off_acc(zb, sj[w][i], lane4, wrow[i], a0,a1,a2,a3);
            }
            __syncwarp();
        }
    }
    s0 = warpSum(s0); s1 = warpSum(s1);
    if (lane==0){ sw0s[w]=s0; sw1s[w]=s1; }
    sacc[w][lane4+0]=a0; sacc[w][lane4+1]=a1;
    sacc[w][lane4+2]=a2; sacc[w][lane4+3]=a3;
    __syncthreads();
    if (tid < EE){
        float r0=0.f, r1=0.f, S0=0.f, S1=0.f;
        #pragma unroll
        for (int ww=0; ww<8; ww++){
            r0 += sacc[ww][tid];
            r1 += sacc[ww][64+tid];
            S0 += sw0s[ww]; S1 += sw1s[ww];
        }
        float v = 0.5f*(r0/S0 + r1/S1);
        g_aggs[((size_t)bn*KK + 1)*EE + tid] = tanhf(v);
    }
}

// ---------------- adj (k=0) aggregation: warp per node --------------------
__global__ __launch_bounds__(256) void K_agg_adj(){
    int w = threadIdx.x>>5, lane = threadIdx.x&31;
    int bn = blockIdx.x*8 + w;
    int b = bn >> 11;
    __shared__ int sj[8][32];
    __shared__ float sw0_[8][32], sw1_[8][32];
    int deg = g_deg_adj[bn];
    const __nv_bfloat16* zb = g_zb + (size_t)b*NN*2*EE;
    float a0=0,a1=0,a2=0,a3=0, ws0=0, ws1=0;
    int lane4 = lane*4;
    if (deg==0){
        for (int j=0;j<NN;j++) bf16off_acc(zb, j*128, lane4, 1.0f, a0,a1,a2,a3);
        ws0 = (float)NN; ws1 = (float)NN;
    } else {
        const unsigned short* list = g_nbr_adj + (size_t)bn*MAXDEG_ADJ;
        float ssrc0 = g_ssrc[bn], ssrc1 = g_ssrc[BB*NN+bn];
        const float* sd0 = g_sdst + b*NN;
        const float* sd1 = g_sdst + BB*NN + b*NN;
        const float* wrow = (lane<16) ? sw0_[w] : sw1_[w];
        for (int base=0; base<deg; base+=32){
            int cnt = deg - base; if (cnt>32) cnt=32;
            float w0 = 0.f, w1 = 0.f;
            if (lane < cnt){
                int j = list[base+lane];
                sj[w][lane] = j*128;
                w0 = __expf(tanhf(ssrc0 + sd0[j]));
                w1 = __expf(tanhf(ssrc1 + sd1[j]));
                sw0_[w][lane]=w0; sw1_[w][lane]=w1;
            }
            ws0 += w0; ws1 += w1;
            __syncwarp();
            #pragma unroll 8
            for (int i=0;i<cnt;i++)
                bf16off_acc(zb, sj[w][i], lane4, wrow[i], a0,a1,a2,a3);
            __syncwarp();
        }
        ws0 = warpSum(ws0); ws1 = warpSum(ws1);
    }
    float b0 = __shfl_down_sync(FULLMASK, a0, 16);
    float b1 = __shfl_down_sync(FULLMASK, a1, 16);
    float b2 = __shfl_down_sync(FULLMASK, a2, 16);
    float b3 = __shfl_down_sync(FULLMASK, a3, 16);
    if (lane < 16){
        float inv0 = 1.0f/ws0, inv1 = 1.0f/ws1;
        float4 o;
        o.x = tanhf(0.5f*(a0*inv0 + b0*inv1));
        o.y = tanhf(0.5f*(a1*inv0 + b1*inv1));
        o.z = tanhf(0.5f*(a2*inv0 + b2*inv1));
        o.w = tanhf(0.5f*(a3*inv0 + b3*inv1));
        *(float4*)(g_aggs + ((size_t)bn*KK+0)*EE + lane*4) = o;
    }
}

// ---------------- GRU as register-tiled GEMM (32 nodes/block) -------------
// Phase A: [nxt; h](128) @ WA(128x128) -> z,r gates
// Phase B: [nxt; r*h](128) @ WB(128x64) -> h_tilde
#define XS 132   // X row stride (pad for bank-conflict-free node access)
#define ZS 68
__global__ __launch_bounds__(256) void K_gru(const float* __restrict__ nbr_q,
                                             const float* __restrict__ gru_W,
                                             const float* __restrict__ gru_U,
                                             const float* __restrict__ gru_b){
    extern __shared__ __align__(16) float dyn[];
    float* WA = dyn;                 // 128*128
    float* WB = dyn + 16384;         // 128*64
    float* X  = dyn + 24576;         // 32*XS
    float* SZ = X + 32*XS;           // 32*ZS (z gate)
    float* HO = SZ + 32*ZS;          // 32*ZS (h_old)
    int tid = threadIdx.x, w = tid>>5, lane = tid&31;

    // load weights: WA[d][e] = d<64 ? W[d][e] : U[d-64][e]   (e in 0..127 = z|r cols)
    for (int i=tid; i<128*128; i+=256){
        int d = i>>7, e = i&127;
        WA[i] = (d<64) ? gru_W[d*192+e] : gru_U[(d-64)*192+e];
    }
    // WB[d][e] = d<64 ? W[d][128+e] : U[d-64][128+e]
    for (int i=tid; i<128*64; i+=256){
        int d = i>>6, e = i&63;
        WB[i] = (d<64) ? gru_W[d*192+128+e] : gru_U[(d-64)*192+128+e];
    }

    // prologue: nxt per node (warp w handles nodes w*4..w*4+3), fill X and HO
    int gn0 = blockIdx.x*32;
    for (int r=0; r<4; r++){
        int ln = w*4 + r;
        int gn = gn0 + ln;
        const float* ag = g_aggs + (size_t)gn*KK*EE;
        float a0_1 = ag[lane],     a0_2 = ag[32+lane];
        float a1_1 = ag[64+lane],  a1_2 = ag[96+lane];
        float q1 = nbr_q[lane], q2 = nbr_q[32+lane];
        float d0 = warpSum(a0_1*q1 + a0_2*q2);
        float d1 = warpSum(a1_1*q1 + a1_2*q2);
        float t0 = tanhf(d0), t1 = tanhf(d1);
        float mx = fmaxf(t0,t1);
        float ex0 = __expf(t0-mx), ex1 = __expf(t1-mx);
        float inv = 1.0f/(ex0+ex1);
        float c0 = ex0*inv, c1 = ex1*inv;
        float h1 = g_h[(size_t)gn*EE+lane], h2 = g_h[(size_t)gn*EE+32+lane];
        X[ln*XS+lane]      = c0*a0_1 + c1*a1_1;
        X[ln*XS+32+lane]   = c0*a0_2 + c1*a1_2;
        X[ln*XS+64+lane]   = h1;
        X[ln*XS+96+lane]   = h2;
        HO[ln*ZS+lane]     = h1;
        HO[ln*ZS+32+lane]  = h2;
    }
    __syncthreads();

    int ng = tid & 7;          // nodes ng, ng+8, ng+16, ng+24
    int eg = tid >> 3;         // output group: e0 = eg*4 (phase A)

    // ---- Phase A: 128 outputs (z,r) ----
    float4 acA0={0,0,0,0}, acA1={0,0,0,0}, acA2={0,0,0,0}, acA3={0,0,0,0};
    {
        const float4* WA4 = (const float4*)WA;   // row = 32 float4
        const float* x0p = X + ng*XS;
        const float* x1p = X + (ng+8)*XS;
        const float* x2p = X + (ng+16)*XS;
        const float* x3p = X + (ng+24)*XS;
        #pragma unroll 4
        for (int d=0; d<128; d++){
            float4 wv = WA4[d*32 + eg];
            float x0 = x0p[d], x1 = x1p[d], x2 = x2p[d], x3 = x3p[d];
            acA0.x += x0*wv.x; acA0.y += x0*wv.y; acA0.z += x0*wv.z; acA0.w += x0*wv.w;
            acA1.x += x1*wv.x; acA1.y += x1*wv.y; acA1.z += x1*wv.z; acA1.w += x1*wv.w;
            acA2.x += x2*wv.x; acA2.y += x2*wv.y; acA2.z += x2*wv.z; acA2.w += x2*wv.w;
            acA3.x += x3*wv.x; acA3.y += x3*wv.y; acA3.z += x3*wv.z; acA3.w += x3*wv.w;
        }
    }
    __syncthreads();
    // epilogue A: sigmoid; e<64 -> z into SZ; e>=64 -> rh into X[64+..]
    {
        int e0 = eg*4;
        float b0v = gru_b[e0], b1v = gru_b[e0+1], b2v = gru_b[e0+2], b3v = gru_b[e0+3];
        float4 accs[4] = {acA0, acA1, acA2, acA3};
        #pragma unroll
        for (int k=0;k<4;k++){
            int n = ng + k*8;
            float v0 = sigmoidf_(accs[k].x + b0v);
            float v1 = sigmoidf_(accs[k].y + b1v);
            float v2 = sigmoidf_(accs[k].z + b2v);
            float v3 = sigmoidf_(accs[k].w + b3v);
            if (e0 < 64){
                SZ[n*ZS+e0]=v0; SZ[n*ZS+e0+1]=v1; SZ[n*ZS+e0+2]=v2; SZ[n*ZS+e0+3]=v3;
            } else {
                int c = 64 + (e0-64);
                X[n*XS+c]   = v0 * X[n*XS+c];
                X[n*XS+c+1] = v1 * X[n*XS+c+1];
                X[n*XS+c+2] = v2 * X[n*XS+c+2];
                X[n*XS+c+3] = v3 * X[n*XS+c+3];
            }
        }
    }
    __syncthreads();

    // ---- Phase B: 64 outputs (h_tilde), 2 per thread ----
    float acB0x=0,acB0y=0, acB1x=0,acB1y=0, acB2x=0,acB2y=0, acB3x=0,acB3y=0;
    {
        const float2* WB2 = (const float2*)WB;   // row = 32 float2
        const float* x0p = X + ng*XS;
        const float* x1p = X + (ng+8)*XS;
        const float* x2p = X + (ng+16)*XS;
        const float* x3p = X + (ng+24)*XS;
        #pragma unroll 4
        for (int d=0; d<128; d++){
            float2 wv = WB2[d*32 + eg];
            float x0 = x0p[d], x1 = x1p[d], x2 = x2p[d], x3 = x3p[d];
            acB0x += x0*wv.x; acB0y += x0*wv.y;
            acB1x += x1*wv.x; acB1y += x1*wv.y;
            acB2x += x2*wv.x; acB2y += x2*wv.y;
            acB3x += x3*wv.x; acB3y += x3*wv.y;
        }
    }
    // epilogue B: h_new = (1-z)*h_old + z*tanh(acc + b)
    {
        int e0 = eg*2;
        float bb0 = gru_b[128+e0], bb1 = gru_b[128+e0+1];
        float bx[4] = {acB0x, acB1x, acB2x, acB3x};
        float by[4] = {acB0y, acB1y, acB2y, acB3y};
        #pragma unroll
        for (int k=0;k<4;k++){
            int n = ng + k*8;
            int gn = gn0 + n;
            float ht0 = tanhf(bx[k] + bb0);
            float ht1 = tanhf(by[k] + bb1);
            float z0 = SZ[n*ZS+e0], z1 = SZ[n*ZS+e0+1];
            float h0 = HO[n*ZS+e0], h1 = HO[n*ZS+e0+1];
            g_h[(size_t)gn*EE+e0]   = (1.0f-z0)*h0 + z0*ht0;
            g_h[(size_t)gn*EE+e0+1] = (1.0f-z1)*h1 + z1*ht1;
        }
    }
}
#define GRU_SMEM ((16384 + 128*64 + 32*XS + 2*32*ZS)*4)

// ---------------- decoder + dual heads + gmax ----------------
__global__ __launch_bounds__(256) void K_dec_dual(const float* __restrict__ dW0, const float* __restrict__ db0,
                                                  const float* __restrict__ dW1, const float* __restrict__ db1,
                                                  const float* __restrict__ uW0, const float* __restrict__ ub0,
                                                  const float* __restrict__ uW1, const float* __restrict__ ub1){
    __shared__ float sWd[EE*EE];
    __shared__ float sWu[EE*EE];
    __shared__ float shh[8][EE];
    int tid = threadIdx.x;
    for (int i=tid;i<EE*EE;i+=256){ sWd[i]=dW0[i]; sWu[i]=uW0[i]; }
    __syncthreads();
    int w = tid>>5, lane = tid&31;
    int e1 = lane, e2 = lane+32;
    #pragma unroll
    for (int rep=0; rep<2; rep++){
        int gn = blockIdx.x*16 + w + rep*8;
        float h1 = g_h[(size_t)gn*EE+e1], h2 = g_h[(size_t)gn*EE+e2];
        shh[w][e1]=h1; shh[w][e2]=h2;
        __syncwarp();
        float t1 = db0[e1], t2 = db0[e2];
        #pragma unroll
        for (int d=0; d<EE; d++){ float hv=shh[w][d]; t1 += hv*sWd[d*EE+e1]; t2 += hv*sWd[d*EE+e2]; }
        t1 = tanhf(t1); t2 = tanhf(t2);
        float p = warpSum(t1*dW1[e1] + t2*dW1[e2]);
        if (lane==0){
            float nwv = p + db1[0];
            g_nw[gn] = nwv;
            unsigned u = __float_as_uint(nwv);
            u = (u & 0x80000000u) ? ~u : (u | 0x80000000u);
            atomicMax(&g_gmaxu[gn>>11], u);
        }
        float u1 = ub0[e1], u2 = ub0[e2];
        #pragma unroll
        for (int d=0; d<EE; d++){ float hv=shh[w][d]; u1 += hv*sWu[d*EE+e1]; u2 += hv*sWu[d*EE+e2]; }
        u1 = tanhf(u1); u2 = tanhf(u2);
        float q = warpSum(u1*uW1[e1] + u2*uW1[e2]);
        if (lane==0) g_dv[gn] = q + ub1[0];
        __syncwarp();
    }
}

// ---------------- softmax denominators + exp(nw) ----------------
__global__ __launch_bounds__(256) void K_prop(){
    int w = threadIdx.x>>5, lane = threadIdx.x&31;
    int gn = blockIdx.x*8 + w;
    int b = gn >> 11;
    unsigned u = g_gmaxu[b];
    float gm = __uint_as_float((u & 0x80000000u) ? (u ^ 0x80000000u) : ~u);
    int deg = g_deg_adj[gn];
    const unsigned short* list = g_nbr_adj + (size_t)gn*MAXDEG_ADJ;
    float s = 0.f;
    for (int t=lane; t<deg; t+=32) s += __expf(g_nw[b*NN + list[t]] - gm);
    s = warpSum(s);
    if (lane==0){
        g_Z[gn] = (deg>0) ? s : 1.0f;
        g_enw[gn] = __expf(g_nw[gn] - gm);
    }
}

// ---------------- fused 10-iteration MCF, reverse-CSR gather --------------
__global__ __launch_bounds__(1024) void K_flow(const float* __restrict__ demands){
    int b = blockIdx.x;
    __shared__ float us[NN];
    int n1 = threadIdx.x, n2 = threadIdx.x + 1024;
    int gn1 = b*NN+n1, gn2 = b*NN+n2;
    float invZ1 = 1.0f/g_Z[gn1], invZ2 = 1.0f/g_Z[gn2];
    float d1 = demands[gn1], d2 = demands[gn2];
    float e1 = g_enw[gn1],  e2 = g_enw[gn2];
    int rd1 = min(g_rdeg[gn1], MAXDEG_IN);
    int rd2 = min(g_rdeg[gn2], MAXDEG_IN);
    const unsigned short* l1 = g_rin + (size_t)gn1*MAXDEG_IN;
    const unsigned short* l2 = g_rin + (size_t)gn2*MAXDEG_IN;
    float s1 = 0.f, s2 = 0.f;
    for (int it=0; it<10; it++){
        us[n1] = s1*invZ1; us[n2] = s2*invZ2;
        __syncthreads();
        float a1 = 0.f, a2 = 0.f;
        for (int t=0; t<rd1; t++) a1 += us[l1[t]];
        for (int t=0; t<rd2; t++) a2 += us[l2[t]];
        s1 = fmaxf(fmaf(e1, a1, -d1), 0.f);
        s2 = fmaxf(fmaf(e2, a2, -d2), 0.f);
        __syncthreads();
    }
    g_s10[gn1] = s1;
    g_s10[gn2] = s2;
}

// ---------------- flow cost + dual iterations + final reduction ----------
__global__ __launch_bounds__(256) void K_final(const float* __restrict__ demands,
                                               float* __restrict__ out){
    int b = blockIdx.y;
    int tid = threadIdx.x, w = tid>>5, lane = tid&31;
    float acc = 0.f;
    for (int idx = w; idx < 64; idx += 8){
        int n = blockIdx.x*64 + idx;
        int gn = b*NN+n;
        int deg = g_deg_adj[gn];
        const unsigned short* list = g_nbr_adj + (size_t)gn*MAXDEG_ADJ;
        float si = g_s10[gn];
        float invZi = 1.0f/g_Z[gn];
        float dvi = g_dv[gn];
        float enwi = g_enw[gn];
        if (lane==0) acc += dvi * demands[gn];
        for (int t=lane; t<deg; t+=32){
            int j = list[t];
            int gj = b*NN+j;
            float f = g_enw[gj]*invZi*si;
            unsigned word = g_adjbit[(size_t)gj*(NN/32) + (n>>5)];
            float ft = 0.f;
            if ((word >> (n&31)) & 1u) ft = enwi * (g_s10[gj]/g_Z[gj]);
            float fp = f - fminf(f, ft);
            acc += fp*fp;
            float dd = dvi - g_dv[gj];
            float y = 0.f, m = 0.f;
            #pragma unroll
            for (int q=0; q<10; q++){
                float gg = 2.0f*y - dd;
                m = 0.9f*m + gg;
                y = fmaxf(y - 0.1f*m, 0.f);
            }
            acc -= (y*y - dd*y);
        }
    }
    acc = warpSum(acc);
    __shared__ float sr[8];
    if (lane==0) sr[w] = acc;
    __syncthreads();
    if (tid==0){
        float t = 0.f; for (int i=0;i<8;i++) t += sr[i];
        atomicAdd(&out[b], t);
    }
}

// ---------------- launch ----------------
extern "C" void kernel_launch(void* const* d_in, const int* in_sizes, int n_in,
                              void* d_out, int out_size){
    const float* feat    = (const float*)d_in[0];
    const float* emb     = (const float*)d_in[1];
    const float* demands = (const float*)d_in[2];
    const float* neigh   = (const float*)d_in[4];
    const float* enc_W0  = (const float*)d_in[5];
    const float* enc_b0  = (const float*)d_in[6];
    const float* enc_W1  = (const float*)d_in[7];
    const float* enc_b1  = (const float*)d_in[8];
    const float* attn_W  = (const float*)d_in[9];
    const float* a_src   = (const float*)d_in[10];
    const float* a_dst   = (const float*)d_in[11];
    const float* nbr_q   = (const float*)d_in[12];
    const float* gru_W   = (const float*)d_in[13];
    const float* gru_U   = (const float*)d_in[14];
    const float* gru_b   = (const float*)d_in[15];
    const float* dec_W0  = (const float*)d_in[16];
    const float* dec_b0  = (const float*)d_in[17];
    const float* dec_W1  = (const float*)d_in[18];
    const float* dec_b1  = (const float*)d_in[19];
    const float* dual_W0 = (const float*)d_in[20];
    const float* dual_b0 = (const float*)d_in[21];
    const float* dual_W1 = (const float*)d_in[22];
    const float* dual_b1 = (const float*)d_in[23];
    float* out = (float*)d_out;

    static int configured = 0;
    if (!configured){
        cudaFuncSetAttribute(K_gru, cudaFuncAttributeMaxDynamicSharedMemorySize, GRU_SMEM);
        configured = 1;
    }

    // NOTE: ncu window captures the 4th launch -> K_agg_a2 (layer 0)
    K_enc<<<BB*NN/4,256>>>(emb, feat, enc_W0, enc_b0, enc_W1, enc_b1, out);
    K_build<<<KK*BB*NN/8,256>>>(neigh);
    for (int l=0;l<2;l++){
        K_z<<<dim3(BB*NN/32,HH),256>>>(attn_W, a_src, a_dst);
        K_agg_a2<<<BB*NN,256>>>();
        K_agg_adj<<<BB*NN/8,256>>>();
        K_gru<<<BB*NN/32,256, GRU_SMEM>>>(nbr_q, gru_W, gru_U, gru_b);
    }
    K_dec_dual<<<BB*NN/16,256>>>(dec_W0,dec_b0,dec_W1,dec_b1,dual_W0,dual_b0,dual_W1,dual_b1);
    K_prop<<<BB*NN/8,256>>>();
    K_flow<<<BB,1024>>>(demands);
    K_final<<<dim3(NN/64,BB),256>>>(demands, out);
}